// round 1
// baseline (speedup 1.0000x reference)
#include <cuda_runtime.h>

// Problem constants
#define TB   8
#define TT   20
#define TN   16
#define TC   1024
#define NPOS 2560          // B*T*N
#define NO   18            // 2*K2

// Scratch (allocation-free rule: __device__ globals)
__device__ float g_wT[2*9*1024*18];      // [ratio][tap][c][o]  (o contiguous)
__device__ float g_offp[3*2*NPOS*NO];    // [tapgroup][ratio][pos][o] partial conv sums
__device__ float g_dynpre[NPOS*TC];      // mean feature before final linear

// ---------------------------------------------------------------------------
// Kernel 1: weight transpose  p_w [18][1024][3][3] -> g_wT [r][tap][c][18]
// ---------------------------------------------------------------------------
__global__ void k_wtrans(const float* __restrict__ w1, const float* __restrict__ w2) {
    int idx = blockIdx.x * 256 + threadIdx.x;
    if (idx >= 2*9*1024*18) return;
    int o   = idx % 18;
    int c   = (idx / 18) % 1024;
    int tap = (idx / (18*1024)) % 9;
    int r   = idx / (18*1024*9);
    const float* w = r ? w2 : w1;
    g_wT[idx] = w[o*9216 + c*9 + tap];
}

// ---------------------------------------------------------------------------
// Kernel 2: offset conv.  grid = (80 pos-tiles of 32) x (2 ratios * 3 tapgroups)
// block = 192 threads = 6 warps. warp w handles outputs {w, w+6, w+12} for
// the 32 positions of the tile (lane <-> position). X tile staged in SMEM
// (c-major, pad 33 -> conflict-free), W chunk staged in SMEM (broadcast reads).
// ---------------------------------------------------------------------------
__global__ void __launch_bounds__(192) k_conv(const float* __restrict__ x) {
    int tile = blockIdx.x;           // 0..79
    int rz   = blockIdx.y;           // 0..5
    int r    = rz / 3;
    int tg   = rz - r*3;
    int ratio = r + 1;

    __shared__ float Xs[32][33];     // [c][pos]
    __shared__ float Ws[576];        // [c][o] chunk (32*18)

    int tid  = threadIdx.x;
    int w    = tid >> 5;             // warp id 0..5
    int lane = tid & 31;             // position slot
    int posg = tile*32 + lane;

    float acc0 = 0.f, acc1 = 0.f, acc2 = 0.f;

    for (int ti = 0; ti < 3; ti++) {
        int tap = tg*3 + ti;
        int kh  = tap/3 - 1;
        int kw  = tap%3 - 1;

        // Precompute per-slot row pointers for the X loads of this tap
        const float* rp[6];
        #pragma unroll
        for (int s = 0; s < 6; s++) {
            int idx = tid + s*192;
            rp[s] = nullptr;
            if (idx < 1024) {
                int pp = idx >> 5, cc = idx & 31;
                int pg = tile*32 + pp;
                int bb = pg / 320; int rem = pg - bb*320;
                int t  = rem >> 4, n = rem & 15;
                int st = t + kh*ratio, sn = n + kw*ratio;
                if ((unsigned)st < (unsigned)TT && (unsigned)sn < (unsigned)TN)
                    rp[s] = x + (((bb*TT + st)*TN + sn)*TC + cc);
            }
        }

        const float* wbase = g_wT + (r*9 + tap)*1024*18;

        for (int c0 = 0; c0 < 1024; c0 += 32) {
            __syncthreads();
            #pragma unroll
            for (int s = 0; s < 6; s++) {
                int idx = tid + s*192;
                if (idx < 1024)
                    Xs[idx & 31][idx >> 5] = rp[s] ? __ldg(rp[s] + c0) : 0.f;
            }
            #pragma unroll
            for (int s = 0; s < 3; s++) {
                int idx = tid + s*192;
                Ws[idx] = wbase[c0*18 + idx];
            }
            __syncthreads();
            #pragma unroll
            for (int cc = 0; cc < 32; cc++) {
                float xv = Xs[cc][lane];
                acc0 = fmaf(xv, Ws[cc*18 + w],      acc0);
                acc1 = fmaf(xv, Ws[cc*18 + w + 6],  acc1);
                acc2 = fmaf(xv, Ws[cc*18 + w + 12], acc2);
            }
        }
    }

    float* dst = g_offp + ((tg*2 + r)*NPOS + posg)*NO;
    dst[w]      = acc0;
    dst[w + 6]  = acc1;
    dst[w + 12] = acc2;
}

// ---------------------------------------------------------------------------
// Kernel 3: per-position deformable bilinear gather.
// Block per position (2560 blocks), 256 threads (thread <-> 4 channels).
// Phase A (18 lanes): finalize offsets (sum 3 partials + bias), compute corner
// indices + bilinear coefficients exactly per reference math.
// Phase B: gather 2 ratios * 9 taps * 4 corners of float4, combine, emit
// ft_mad (ratio 2) and accumulate the /18 mean into g_dynpre.
// ---------------------------------------------------------------------------
__global__ void __launch_bounds__(256) k_gather(const float* __restrict__ x,
                                                const float* __restrict__ b1,
                                                const float* __restrict__ b2,
                                                float* __restrict__ out_ftmad,
                                                int write_ftmad) {
    int pos = blockIdx.x;
    int bb  = pos / 320; int rem = pos - bb*320;
    int t   = rem >> 4,  n = rem & 15;

    __shared__ int   s_off[2][9][4];
    __shared__ float s_coe[2][9][4];

    int tid = threadIdx.x;
    if (tid < 18) {
        int r = tid / 9, k = tid - r*9;
        int ratio = r + 1;
        const float* bias = r ? b2 : b1;
        float offt = bias[k], offn = bias[k + 9];
        #pragma unroll
        for (int tg = 0; tg < 3; tg++) {
            const float* op = g_offp + ((tg*2 + r)*NPOS + pos)*NO;
            offt += op[k];
            offn += op[k + 9];
        }
        float Tp1 = (float)(TT + 2*ratio - 1);
        float Np1 = (float)(TN + 2*ratio - 1);
        float post = (float)(t + ratio) + (float)((k/3 - 1)*ratio) + offt;
        float posn = (float)(n + ratio) + (float)((k%3 - 1)*ratio) + offn;
        float flt = floorf(post), fln = floorf(posn);
        float ltt = fminf(fmaxf(flt,       0.f), Tp1);
        float ltn = fminf(fmaxf(fln,       0.f), Np1);
        float rbt = fminf(fmaxf(flt + 1.f, 0.f), Tp1);
        float rbn = fminf(fmaxf(fln + 1.f, 0.f), Np1);
        float pct = fminf(fmaxf(post, 0.f), Tp1);
        float pcn = fminf(fmaxf(posn, 0.f), Np1);
        float wltt = 1.f - fabsf(pct - ltt);
        float wrbt = 1.f - fabsf(pct - rbt);
        float wltn = 1.f - fabsf(pcn - ltn);
        float wrbn = 1.f - fabsf(pcn - rbn);
        s_coe[r][k][0] = wltt * wltn;   // lt
        s_coe[r][k][1] = wrbt * wrbn;   // rb
        s_coe[r][k][2] = wrbt * wltn;   // lb  (rb_t, lt_n)
        s_coe[r][k][3] = wltt * wrbn;   // rt  (lt_t, rb_n)
        int ict[4] = {(int)ltt, (int)rbt, (int)rbt, (int)ltt};
        int icn[4] = {(int)ltn, (int)rbn, (int)ltn, (int)rbn};
        #pragma unroll
        for (int q = 0; q < 4; q++) {
            int ts = ict[q] - ratio, ns = icn[q] - ratio;   // padded -> source
            s_off[r][k][q] = ((unsigned)ts < (unsigned)TT && (unsigned)ns < (unsigned)TN)
                           ? ((bb*TT + ts)*TN + ns)*TC : -1;
        }
    }
    __syncthreads();

    int c = tid * 4;
    float dx = 0.f, dy = 0.f, dz = 0.f, dw = 0.f;
    #pragma unroll
    for (int r = 0; r < 2; r++) {
        #pragma unroll
        for (int k = 0; k < 9; k++) {
            float fx = 0.f, fy = 0.f, fz = 0.f, fw = 0.f;
            #pragma unroll
            for (int q = 0; q < 4; q++) {
                int   o   = s_off[r][k][q];
                float coe = s_coe[r][k][q];
                if (o >= 0) {   // uniform across block -> no divergence
                    float4 v = *(const float4*)(x + o + c);
                    fx = fmaf(coe, v.x, fx);
                    fy = fmaf(coe, v.y, fy);
                    fz = fmaf(coe, v.z, fz);
                    fw = fmaf(coe, v.w, fw);
                }
            }
            if (r == 1 && write_ftmad) {
                float4 ov = make_float4(fx, fy, fz, fw);
                *(float4*)(out_ftmad + (pos*9 + k)*1024 + c) = ov;
            }
            dx += fx; dy += fy; dz += fz; dw += fw;
        }
    }
    const float s = 1.f / 18.f;   // mean over 9 taps and 2 ratios
    float4 dv = make_float4(dx*s, dy*s, dz*s, dw*s);
    *(float4*)(g_dynpre + pos*1024 + c) = dv;
}

// ---------------------------------------------------------------------------
// Kernel 4: SGEMM  out[2560][1024] = g_dynpre @ W_hidden^T  (both K-contiguous)
// Tile 64(M) x 128(N) x 8(K), 256 threads, 4x8 register microtile.
// ---------------------------------------------------------------------------
__global__ void __launch_bounds__(256) k_gemm(const float* __restrict__ W,
                                              float* __restrict__ out) {
    __shared__ float As[8][64];
    __shared__ float Bs[8][128];
    int bx = blockIdx.x;             // 0..7   (N tiles)
    int by = blockIdx.y;             // 0..39  (M tiles)
    int tid = threadIdx.x;
    int tx = tid & 15, ty = tid >> 4;
    int arow = tid >> 1;
    int akq  = (tid & 1) * 4;

    const float* Aptr = g_dynpre + ((long)(by*64 + (arow & 63)))*1024 + akq;
    const float* Wptr = W        + ((long)(bx*128 + arow))*1024 + akq;

    float acc[4][8];
    #pragma unroll
    for (int i = 0; i < 4; i++)
        #pragma unroll
        for (int j = 0; j < 8; j++) acc[i][j] = 0.f;

    for (int k0 = 0; k0 < 1024; k0 += 8) {
        __syncthreads();
        if (tid < 128) {
            float4 a4 = *(const float4*)(Aptr + k0);
            As[akq+0][arow] = a4.x; As[akq+1][arow] = a4.y;
            As[akq+2][arow] = a4.z; As[akq+3][arow] = a4.w;
        }
        {
            float4 b4 = *(const float4*)(Wptr + k0);
            Bs[akq+0][arow] = b4.x; Bs[akq+1][arow] = b4.y;
            Bs[akq+2][arow] = b4.z; Bs[akq+3][arow] = b4.w;
        }
        __syncthreads();
        #pragma unroll
        for (int kk = 0; kk < 8; kk++) {
            float a[4], bv[8];
            *(float4*)a      = *(const float4*)&As[kk][ty*4];
            *(float4*)&bv[0] = *(const float4*)&Bs[kk][tx*8];
            *(float4*)&bv[4] = *(const float4*)&Bs[kk][tx*8 + 4];
            #pragma unroll
            for (int i = 0; i < 4; i++)
                #pragma unroll
                for (int j = 0; j < 8; j++)
                    acc[i][j] = fmaf(a[i], bv[j], acc[i][j]);
        }
    }

    #pragma unroll
    for (int i = 0; i < 4; i++) {
        float* dst = out + ((long)(by*64 + ty*4 + i))*1024 + bx*128 + tx*8;
        float4 o0 = make_float4(acc[i][0], acc[i][1], acc[i][2], acc[i][3]);
        float4 o1 = make_float4(acc[i][4], acc[i][5], acc[i][6], acc[i][7]);
        *(float4*)dst       = o0;
        *(float4*)(dst + 4) = o1;
    }
}

// ---------------------------------------------------------------------------
extern "C" void kernel_launch(void* const* d_in, const int* in_sizes, int n_in,
                              void* d_out, int out_size) {
    const float* xf  = (const float*)d_in[0];  // person_features [8,20,16,1024]
    const float* Wh  = (const float*)d_in[1];  // W_hidden [1024,1024]
    const float* w1  = (const float*)d_in[2];  // p_w1 [18,1024,3,3]
    const float* bb1 = (const float*)d_in[3];  // p_b1 [18]
    const float* w2  = (const float*)d_in[4];  // p_w2 [18,1024,3,3]
    const float* bb2 = (const float*)d_in[5];  // p_b2 [18]
    (void)in_sizes; (void)n_in;

    float* out       = (float*)d_out;
    float* out_dyn   = out;                       // [2560,1024]
    float* out_ftmad = out + (long)NPOS * TC;     // [2560,9,1024]
    int write_ftmad  = (out_size >= NPOS*TC + NPOS*9*TC) ? 1 : 0;

    k_wtrans<<<(2*9*1024*18 + 255)/256, 256>>>(w1, w2);

    dim3 gconv(80, 6);
    k_conv<<<gconv, 192>>>(xf);

    k_gather<<<NPOS, 256>>>(xf, bb1, bb2, out_ftmad, write_ftmad);

    dim3 ggemm(8, 40);
    k_gemm<<<ggemm, 256>>>(Wh, out_dyn);
}

// round 2
// speedup vs baseline: 1.1464x; 1.1464x over previous
#include <cuda_runtime.h>

// Problem constants
#define TB   8
#define TT   20
#define TN   16
#define TC   1024
#define NPOS 2560          // B*T*N
#define NO   18            // 2*K2

// Scratch (allocation-free rule: __device__ globals)
__device__ float g_wT[2*9*1024*18];      // [ratio][tap][c][o]  (o contiguous)
__device__ float g_offp[3*2*NPOS*NO];    // [tapgroup][ratio][pos][o] partial conv sums
__device__ float g_dynpre[NPOS*TC];      // mean feature before final linear

// ---- packed fp32x2 helpers (sm_103a FFMA2) --------------------------------
__device__ __forceinline__ void ffma2(unsigned long long& acc,
                                      unsigned long long a,
                                      unsigned long long b) {
    asm("fma.rn.f32x2 %0, %1, %2, %0;" : "+l"(acc) : "l"(a), "l"(b));
}
__device__ __forceinline__ unsigned long long packdup(float v) {
    unsigned long long r;
    asm("mov.b64 %0, {%1, %2};" : "=l"(r) : "f"(v), "f"(v));
    return r;
}
__device__ __forceinline__ float2 unpack2(unsigned long long v) {
    float2 r;
    asm("mov.b64 {%0, %1}, %2;" : "=f"(r.x), "=f"(r.y) : "l"(v));
    return r;
}

// ---------------------------------------------------------------------------
// Kernel 1: weight transpose  p_w [18][1024][3][3] -> g_wT [r][tap][c][18]
// ---------------------------------------------------------------------------
__global__ void k_wtrans(const float* __restrict__ w1, const float* __restrict__ w2) {
    int idx = blockIdx.x * 256 + threadIdx.x;
    if (idx >= 2*9*1024*18) return;
    int o   = idx % 18;
    int c   = (idx / 18) % 1024;
    int tap = (idx / (18*1024)) % 9;
    int r   = idx / (18*1024*9);
    const float* w = r ? w2 : w1;
    g_wT[idx] = w[o*9216 + c*9 + tap];
}

// ---------------------------------------------------------------------------
// Kernel 2: offset conv.  grid = (80 pos-tiles of 32) x (2 ratios * 3 tapgroups)
// ---------------------------------------------------------------------------
__global__ void __launch_bounds__(192) k_conv(const float* __restrict__ x) {
    int tile = blockIdx.x;           // 0..79
    int rz   = blockIdx.y;           // 0..5
    int r    = rz / 3;
    int tg   = rz - r*3;
    int ratio = r + 1;

    __shared__ float Xs[32][33];     // [c][pos]
    __shared__ float Ws[576];        // [c][o] chunk (32*18)

    int tid  = threadIdx.x;
    int w    = tid >> 5;             // warp id 0..5
    int lane = tid & 31;             // position slot
    int posg = tile*32 + lane;

    float acc0 = 0.f, acc1 = 0.f, acc2 = 0.f;

    for (int ti = 0; ti < 3; ti++) {
        int tap = tg*3 + ti;
        int kh  = tap/3 - 1;
        int kw  = tap%3 - 1;

        const float* rp[6];
        #pragma unroll
        for (int s = 0; s < 6; s++) {
            int idx = tid + s*192;
            rp[s] = nullptr;
            if (idx < 1024) {
                int pp = idx >> 5, cc = idx & 31;
                int pg = tile*32 + pp;
                int bb = pg / 320; int rem = pg - bb*320;
                int t  = rem >> 4, n = rem & 15;
                int st = t + kh*ratio, sn = n + kw*ratio;
                if ((unsigned)st < (unsigned)TT && (unsigned)sn < (unsigned)TN)
                    rp[s] = x + (((bb*TT + st)*TN + sn)*TC + cc);
            }
        }

        const float* wbase = g_wT + (r*9 + tap)*1024*18;

        for (int c0 = 0; c0 < 1024; c0 += 32) {
            __syncthreads();
            #pragma unroll
            for (int s = 0; s < 6; s++) {
                int idx = tid + s*192;
                if (idx < 1024)
                    Xs[idx & 31][idx >> 5] = rp[s] ? __ldg(rp[s] + c0) : 0.f;
            }
            #pragma unroll
            for (int s = 0; s < 3; s++) {
                int idx = tid + s*192;
                Ws[idx] = wbase[c0*18 + idx];
            }
            __syncthreads();
            #pragma unroll
            for (int cc = 0; cc < 32; cc++) {
                float xv = Xs[cc][lane];
                acc0 = fmaf(xv, Ws[cc*18 + w],      acc0);
                acc1 = fmaf(xv, Ws[cc*18 + w + 6],  acc1);
                acc2 = fmaf(xv, Ws[cc*18 + w + 12], acc2);
            }
        }
    }

    float* dst = g_offp + ((tg*2 + r)*NPOS + posg)*NO;
    dst[w]      = acc0;
    dst[w + 6]  = acc1;
    dst[w + 12] = acc2;
}

// ---------------------------------------------------------------------------
// Kernel 3: per-position deformable bilinear gather (unchanged; L2-BW bound)
// ---------------------------------------------------------------------------
__global__ void __launch_bounds__(256) k_gather(const float* __restrict__ x,
                                                const float* __restrict__ b1,
                                                const float* __restrict__ b2,
                                                float* __restrict__ out_ftmad,
                                                int write_ftmad) {
    int pos = blockIdx.x;
    int bb  = pos / 320; int rem = pos - bb*320;
    int t   = rem >> 4,  n = rem & 15;

    __shared__ int   s_off[2][9][4];
    __shared__ float s_coe[2][9][4];

    int tid = threadIdx.x;
    if (tid < 18) {
        int r = tid / 9, k = tid - r*9;
        int ratio = r + 1;
        const float* bias = r ? b2 : b1;
        float offt = bias[k], offn = bias[k + 9];
        #pragma unroll
        for (int tg = 0; tg < 3; tg++) {
            const float* op = g_offp + ((tg*2 + r)*NPOS + pos)*NO;
            offt += op[k];
            offn += op[k + 9];
        }
        float Tp1 = (float)(TT + 2*ratio - 1);
        float Np1 = (float)(TN + 2*ratio - 1);
        float post = (float)(t + ratio) + (float)((k/3 - 1)*ratio) + offt;
        float posn = (float)(n + ratio) + (float)((k%3 - 1)*ratio) + offn;
        float flt = floorf(post), fln = floorf(posn);
        float ltt = fminf(fmaxf(flt,       0.f), Tp1);
        float ltn = fminf(fmaxf(fln,       0.f), Np1);
        float rbt = fminf(fmaxf(flt + 1.f, 0.f), Tp1);
        float rbn = fminf(fmaxf(fln + 1.f, 0.f), Np1);
        float pct = fminf(fmaxf(post, 0.f), Tp1);
        float pcn = fminf(fmaxf(posn, 0.f), Np1);
        float wltt = 1.f - fabsf(pct - ltt);
        float wrbt = 1.f - fabsf(pct - rbt);
        float wltn = 1.f - fabsf(pcn - ltn);
        float wrbn = 1.f - fabsf(pcn - rbn);
        s_coe[r][k][0] = wltt * wltn;   // lt
        s_coe[r][k][1] = wrbt * wrbn;   // rb
        s_coe[r][k][2] = wrbt * wltn;   // lb  (rb_t, lt_n)
        s_coe[r][k][3] = wltt * wrbn;   // rt  (lt_t, rb_n)
        int ict[4] = {(int)ltt, (int)rbt, (int)rbt, (int)ltt};
        int icn[4] = {(int)ltn, (int)rbn, (int)ltn, (int)rbn};
        #pragma unroll
        for (int q = 0; q < 4; q++) {
            int ts = ict[q] - ratio, ns = icn[q] - ratio;   // padded -> source
            s_off[r][k][q] = ((unsigned)ts < (unsigned)TT && (unsigned)ns < (unsigned)TN)
                           ? ((bb*TT + ts)*TN + ns)*TC : -1;
        }
    }
    __syncthreads();

    int c = tid * 4;
    float dx = 0.f, dy = 0.f, dz = 0.f, dw = 0.f;
    #pragma unroll
    for (int r = 0; r < 2; r++) {
        #pragma unroll
        for (int k = 0; k < 9; k++) {
            float fx = 0.f, fy = 0.f, fz = 0.f, fw = 0.f;
            #pragma unroll
            for (int q = 0; q < 4; q++) {
                int   o   = s_off[r][k][q];
                float coe = s_coe[r][k][q];
                if (o >= 0) {   // uniform across block -> no divergence
                    float4 v = *(const float4*)(x + o + c);
                    fx = fmaf(coe, v.x, fx);
                    fy = fmaf(coe, v.y, fy);
                    fz = fmaf(coe, v.z, fz);
                    fw = fmaf(coe, v.w, fw);
                }
            }
            if (r == 1 && write_ftmad) {
                float4 ov = make_float4(fx, fy, fz, fw);
                *(float4*)(out_ftmad + (pos*9 + k)*1024 + c) = ov;
            }
            dx += fx; dy += fy; dz += fz; dw += fw;
        }
    }
    const float s = 1.f / 18.f;   // mean over 9 taps and 2 ratios
    float4 dv = make_float4(dx*s, dy*s, dz*s, dw*s);
    *(float4*)(g_dynpre + pos*1024 + c) = dv;
}

// ---------------------------------------------------------------------------
// Kernel 4: SGEMM  out[2560][1024] = g_dynpre @ W_hidden^T
// 128x128x8 tile, 256 threads, 8x8 microtile in packed f32x2 (FFMA2),
// double-buffered SMEM + register prefetch, 1 sync per K-step.
// ---------------------------------------------------------------------------
__global__ void __launch_bounds__(256, 2) k_gemm(const float* __restrict__ W,
                                                 float* __restrict__ out) {
    __shared__ float As[2][8][128];
    __shared__ float Bs[2][8][128];

    int bx = blockIdx.x;             // 0..7   (N tiles)
    int by = blockIdx.y;             // 0..19  (M tiles)
    int tid = threadIdx.x;
    int tx = tid & 15, ty = tid >> 4;
    int lrow = tid >> 1;             // 0..127
    int lkq  = (tid & 1) * 4;        // 0 or 4

    const float* Aptr = g_dynpre + (long)(by*128 + lrow)*1024 + lkq;
    const float* Wptr = W        + (long)(bx*128 + lrow)*1024 + lkq;

    unsigned long long acc[8][4];
    #pragma unroll
    for (int i = 0; i < 8; i++)
        #pragma unroll
        for (int j = 0; j < 4; j++) acc[i][j] = 0ULL;

    // preload first K-slab into buffer 0
    float4 pa = *(const float4*)Aptr;
    float4 pb = *(const float4*)Wptr;
    As[0][lkq+0][lrow] = pa.x; As[0][lkq+1][lrow] = pa.y;
    As[0][lkq+2][lrow] = pa.z; As[0][lkq+3][lrow] = pa.w;
    Bs[0][lkq+0][lrow] = pb.x; Bs[0][lkq+1][lrow] = pb.y;
    Bs[0][lkq+2][lrow] = pb.z; Bs[0][lkq+3][lrow] = pb.w;
    __syncthreads();

    int cur = 0;
    for (int k0 = 8; k0 <= 1024; k0 += 8) {
        bool more = (k0 < 1024);
        if (more) {
            pa = *(const float4*)(Aptr + k0);
            pb = *(const float4*)(Wptr + k0);
        }
        #pragma unroll
        for (int kk = 0; kk < 8; kk++) {
            float4 a0 = *(const float4*)&As[cur][kk][ty*8];
            float4 a1 = *(const float4*)&As[cur][kk][ty*8 + 4];
            ulonglong2 b01 = *(const ulonglong2*)&Bs[cur][kk][tx*8];
            ulonglong2 b23 = *(const ulonglong2*)&Bs[cur][kk][tx*8 + 4];
            float av[8] = {a0.x, a0.y, a0.z, a0.w, a1.x, a1.y, a1.z, a1.w};
            #pragma unroll
            for (int i = 0; i < 8; i++) {
                unsigned long long aa = packdup(av[i]);
                ffma2(acc[i][0], aa, b01.x);
                ffma2(acc[i][1], aa, b01.y);
                ffma2(acc[i][2], aa, b23.x);
                ffma2(acc[i][3], aa, b23.y);
            }
        }
        if (more) {
            int nxt = cur ^ 1;
            As[nxt][lkq+0][lrow] = pa.x; As[nxt][lkq+1][lrow] = pa.y;
            As[nxt][lkq+2][lrow] = pa.z; As[nxt][lkq+3][lrow] = pa.w;
            Bs[nxt][lkq+0][lrow] = pb.x; Bs[nxt][lkq+1][lrow] = pb.y;
            Bs[nxt][lkq+2][lrow] = pb.z; Bs[nxt][lkq+3][lrow] = pb.w;
            __syncthreads();
            cur = nxt;
        }
    }

    #pragma unroll
    for (int i = 0; i < 8; i++) {
        float2 p0 = unpack2(acc[i][0]);
        float2 p1 = unpack2(acc[i][1]);
        float2 p2 = unpack2(acc[i][2]);
        float2 p3 = unpack2(acc[i][3]);
        float* dst = out + (long)(by*128 + ty*8 + i)*1024 + bx*128 + tx*8;
        *(float4*)dst       = make_float4(p0.x, p0.y, p1.x, p1.y);
        *(float4*)(dst + 4) = make_float4(p2.x, p2.y, p3.x, p3.y);
    }
}

// ---------------------------------------------------------------------------
extern "C" void kernel_launch(void* const* d_in, const int* in_sizes, int n_in,
                              void* d_out, int out_size) {
    const float* xf  = (const float*)d_in[0];  // person_features [8,20,16,1024]
    const float* Wh  = (const float*)d_in[1];  // W_hidden [1024,1024]
    const float* w1  = (const float*)d_in[2];  // p_w1 [18,1024,3,3]
    const float* bb1 = (const float*)d_in[3];  // p_b1 [18]
    const float* w2  = (const float*)d_in[4];  // p_w2 [18,1024,3,3]
    const float* bb2 = (const float*)d_in[5];  // p_b2 [18]
    (void)in_sizes; (void)n_in;

    float* out       = (float*)d_out;
    float* out_dyn   = out;                       // [2560,1024]
    float* out_ftmad = out + (long)NPOS * TC;     // [2560,9,1024]
    int write_ftmad  = (out_size >= NPOS*TC + NPOS*9*TC) ? 1 : 0;

    k_wtrans<<<(2*9*1024*18 + 255)/256, 256>>>(w1, w2);

    dim3 gconv(80, 6);
    k_conv<<<gconv, 192>>>(xf);

    k_gather<<<NPOS, 256>>>(xf, bb1, bb2, out_ftmad, write_ftmad);

    dim3 ggemm(8, 20);
    k_gemm<<<ggemm, 256>>>(Wh, out_dyn);
}

// round 3
// speedup vs baseline: 1.2193x; 1.0636x over previous
#include <cuda_runtime.h>

// Problem constants
#define TB   8
#define TT   20
#define TN   16
#define TC   1024
#define NPOS 2560          // B*T*N
#define NO   18            // 2*K2

// Scratch (allocation-free rule: __device__ globals)
__device__ float g_wT[2*9*1024*18];      // [ratio][tap][c][o]  (o contiguous)
__device__ float g_offp[3*2*NPOS*NO];    // [tapgroup][ratio][pos][o] partial conv sums
__device__ float g_dynpre[NPOS*TC];      // mean feature before final linear

// ---- packed fp32x2 helpers (sm_103a FFMA2) --------------------------------
__device__ __forceinline__ void ffma2(unsigned long long& acc,
                                      unsigned long long a,
                                      unsigned long long b) {
    asm("fma.rn.f32x2 %0, %1, %2, %0;" : "+l"(acc) : "l"(a), "l"(b));
}
__device__ __forceinline__ unsigned long long packdup(float v) {
    unsigned long long r;
    asm("mov.b64 %0, {%1, %2};" : "=l"(r) : "f"(v), "f"(v));
    return r;
}
__device__ __forceinline__ float2 unpack2(unsigned long long v) {
    float2 r;
    asm("mov.b64 {%0, %1}, %2;" : "=f"(r.x), "=f"(r.y) : "l"(v));
    return r;
}

// ---------------------------------------------------------------------------
// Kernel 1: weight transpose  p_w [18][1024][3][3] -> g_wT [r][tap][c][18]
// ---------------------------------------------------------------------------
__global__ void k_wtrans(const float* __restrict__ w1, const float* __restrict__ w2) {
    int idx = blockIdx.x * 256 + threadIdx.x;
    if (idx >= 2*9*1024*18) return;
    int o   = idx % 18;
    int c   = (idx / 18) % 1024;
    int tap = (idx / (18*1024)) % 9;
    int r   = idx / (18*1024*9);
    const float* w = r ? w2 : w1;
    g_wT[idx] = w[o*9216 + c*9 + tap];
}

// ---------------------------------------------------------------------------
// Kernel 2: offset conv.  grid = (80 pos-tiles of 32) x (2 ratios * 3 tapgroups)
// ---------------------------------------------------------------------------
__global__ void __launch_bounds__(192) k_conv(const float* __restrict__ x) {
    int tile = blockIdx.x;           // 0..79
    int rz   = blockIdx.y;           // 0..5
    int r    = rz / 3;
    int tg   = rz - r*3;
    int ratio = r + 1;

    __shared__ float Xs[32][33];     // [c][pos]
    __shared__ float Ws[576];        // [c][o] chunk (32*18)

    int tid  = threadIdx.x;
    int w    = tid >> 5;             // warp id 0..5
    int lane = tid & 31;             // position slot
    int posg = tile*32 + lane;

    float acc0 = 0.f, acc1 = 0.f, acc2 = 0.f;

    for (int ti = 0; ti < 3; ti++) {
        int tap = tg*3 + ti;
        int kh  = tap/3 - 1;
        int kw  = tap%3 - 1;

        const float* rp[6];
        #pragma unroll
        for (int s = 0; s < 6; s++) {
            int idx = tid + s*192;
            rp[s] = nullptr;
            if (idx < 1024) {
                int pp = idx >> 5, cc = idx & 31;
                int pg = tile*32 + pp;
                int bb = pg / 320; int rem = pg - bb*320;
                int t  = rem >> 4, n = rem & 15;
                int st = t + kh*ratio, sn = n + kw*ratio;
                if ((unsigned)st < (unsigned)TT && (unsigned)sn < (unsigned)TN)
                    rp[s] = x + (((bb*TT + st)*TN + sn)*TC + cc);
            }
        }

        const float* wbase = g_wT + (r*9 + tap)*1024*18;

        for (int c0 = 0; c0 < 1024; c0 += 32) {
            __syncthreads();
            #pragma unroll
            for (int s = 0; s < 6; s++) {
                int idx = tid + s*192;
                if (idx < 1024)
                    Xs[idx & 31][idx >> 5] = rp[s] ? __ldg(rp[s] + c0) : 0.f;
            }
            #pragma unroll
            for (int s = 0; s < 3; s++) {
                int idx = tid + s*192;
                Ws[idx] = wbase[c0*18 + idx];
            }
            __syncthreads();
            #pragma unroll
            for (int cc = 0; cc < 32; cc++) {
                float xv = Xs[cc][lane];
                acc0 = fmaf(xv, Ws[cc*18 + w],      acc0);
                acc1 = fmaf(xv, Ws[cc*18 + w + 6],  acc1);
                acc2 = fmaf(xv, Ws[cc*18 + w + 12], acc2);
            }
        }
    }

    float* dst = g_offp + ((tg*2 + r)*NPOS + posg)*NO;
    dst[w]      = acc0;
    dst[w + 6]  = acc1;
    dst[w + 12] = acc2;
}

// ---------------------------------------------------------------------------
// Kernel 3: per-position deformable bilinear gather (L2-BW bound)
// ---------------------------------------------------------------------------
__global__ void __launch_bounds__(256) k_gather(const float* __restrict__ x,
                                                const float* __restrict__ b1,
                                                const float* __restrict__ b2,
                                                float* __restrict__ out_ftmad,
                                                int write_ftmad) {
    int pos = blockIdx.x;
    int bb  = pos / 320; int rem = pos - bb*320;
    int t   = rem >> 4,  n = rem & 15;

    __shared__ int   s_off[2][9][4];
    __shared__ float s_coe[2][9][4];

    int tid = threadIdx.x;
    if (tid < 18) {
        int r = tid / 9, k = tid - r*9;
        int ratio = r + 1;
        const float* bias = r ? b2 : b1;
        float offt = bias[k], offn = bias[k + 9];
        #pragma unroll
        for (int tg = 0; tg < 3; tg++) {
            const float* op = g_offp + ((tg*2 + r)*NPOS + pos)*NO;
            offt += op[k];
            offn += op[k + 9];
        }
        float Tp1 = (float)(TT + 2*ratio - 1);
        float Np1 = (float)(TN + 2*ratio - 1);
        float post = (float)(t + ratio) + (float)((k/3 - 1)*ratio) + offt;
        float posn = (float)(n + ratio) + (float)((k%3 - 1)*ratio) + offn;
        float flt = floorf(post), fln = floorf(posn);
        float ltt = fminf(fmaxf(flt,       0.f), Tp1);
        float ltn = fminf(fmaxf(fln,       0.f), Np1);
        float rbt = fminf(fmaxf(flt + 1.f, 0.f), Tp1);
        float rbn = fminf(fmaxf(fln + 1.f, 0.f), Np1);
        float pct = fminf(fmaxf(post, 0.f), Tp1);
        float pcn = fminf(fmaxf(posn, 0.f), Np1);
        float wltt = 1.f - fabsf(pct - ltt);
        float wrbt = 1.f - fabsf(pct - rbt);
        float wltn = 1.f - fabsf(pcn - ltn);
        float wrbn = 1.f - fabsf(pcn - rbn);
        s_coe[r][k][0] = wltt * wltn;   // lt
        s_coe[r][k][1] = wrbt * wrbn;   // rb
        s_coe[r][k][2] = wrbt * wltn;   // lb  (rb_t, lt_n)
        s_coe[r][k][3] = wltt * wrbn;   // rt  (lt_t, rb_n)
        int ict[4] = {(int)ltt, (int)rbt, (int)rbt, (int)ltt};
        int icn[4] = {(int)ltn, (int)rbn, (int)ltn, (int)rbn};
        #pragma unroll
        for (int q = 0; q < 4; q++) {
            int ts = ict[q] - ratio, ns = icn[q] - ratio;   // padded -> source
            s_off[r][k][q] = ((unsigned)ts < (unsigned)TT && (unsigned)ns < (unsigned)TN)
                           ? ((bb*TT + ts)*TN + ns)*TC : -1;
        }
    }
    __syncthreads();

    int c = tid * 4;
    float dx = 0.f, dy = 0.f, dz = 0.f, dw = 0.f;
    #pragma unroll
    for (int r = 0; r < 2; r++) {
        #pragma unroll
        for (int k = 0; k < 9; k++) {
            float fx = 0.f, fy = 0.f, fz = 0.f, fw = 0.f;
            #pragma unroll
            for (int q = 0; q < 4; q++) {
                int   o   = s_off[r][k][q];
                float coe = s_coe[r][k][q];
                if (o >= 0) {   // uniform across block -> no divergence
                    float4 v = *(const float4*)(x + o + c);
                    fx = fmaf(coe, v.x, fx);
                    fy = fmaf(coe, v.y, fy);
                    fz = fmaf(coe, v.z, fz);
                    fw = fmaf(coe, v.w, fw);
                }
            }
            if (r == 1 && write_ftmad) {
                float4 ov = make_float4(fx, fy, fz, fw);
                *(float4*)(out_ftmad + (pos*9 + k)*1024 + c) = ov;
            }
            dx += fx; dy += fy; dz += fz; dw += fw;
        }
    }
    const float s = 1.f / 18.f;   // mean over 9 taps and 2 ratios
    float4 dv = make_float4(dx*s, dy*s, dz*s, dw*s);
    *(float4*)(g_dynpre + pos*1024 + c) = dv;
}

// ---------------------------------------------------------------------------
// Kernel 4: SGEMM  out[2560][1024] = g_dynpre @ W_hidden^T
// 128(M) x 64(N) x 16(K) tile, 256 threads, 8x4 microtile in packed f32x2,
// double-buffered SMEM + register prefetch. grid = 20x16 = 320 CTAs.
// ---------------------------------------------------------------------------
__global__ void __launch_bounds__(256, 3) k_gemm(const float* __restrict__ W,
                                                 float* __restrict__ out) {
    __shared__ float As[2][16][128];
    __shared__ float Bs[2][16][64];

    int bx = blockIdx.x;             // 0..15  (N tiles of 64)
    int by = blockIdx.y;             // 0..19  (M tiles of 128)
    int tid = threadIdx.x;
    int tx = tid & 15;               // N group (4 cols each)
    int ty = tid >> 4;               // M group (8 rows each)

    // A loader: each thread 2x float4 : row = tid>>1, k = (tid&1)*4 and +8
    int arow = tid >> 1;
    int ak   = (tid & 1) * 4;
    // B loader: each thread 1x float4 : row = tid&63, k = (tid>>6)*4
    int brow = tid & 63;
    int bk   = (tid >> 6) * 4;

    const float* Aptr = g_dynpre + (long)(by*128 + arow)*1024 + ak;
    const float* Wptr = W        + (long)(bx*64  + brow)*1024 + bk;

    unsigned long long acc[8][2];
    #pragma unroll
    for (int i = 0; i < 8; i++) { acc[i][0] = 0ULL; acc[i][1] = 0ULL; }

    // preload slab 0
    float4 pa0 = *(const float4*)Aptr;
    float4 pa1 = *(const float4*)(Aptr + 8);
    float4 pb  = *(const float4*)Wptr;
    #pragma unroll
    for (int q = 0; q < 4; q++) {
        As[0][ak + q][arow]     = ((const float*)&pa0)[q];
        As[0][ak + 8 + q][arow] = ((const float*)&pa1)[q];
        Bs[0][bk + q][brow]     = ((const float*)&pb)[q];
    }
    __syncthreads();

    int cur = 0;
    for (int k0 = 16; k0 <= 1024; k0 += 16) {
        bool more = (k0 < 1024);
        if (more) {
            pa0 = *(const float4*)(Aptr + k0);
            pa1 = *(const float4*)(Aptr + k0 + 8);
            pb  = *(const float4*)(Wptr + k0);
        }
        #pragma unroll
        for (int kk = 0; kk < 16; kk++) {
            float4 a0 = *(const float4*)&As[cur][kk][ty*8];
            float4 a1 = *(const float4*)&As[cur][kk][ty*8 + 4];
            ulonglong2 b = *(const ulonglong2*)&Bs[cur][kk][tx*4];
            float av[8] = {a0.x, a0.y, a0.z, a0.w, a1.x, a1.y, a1.z, a1.w};
            #pragma unroll
            for (int i = 0; i < 8; i++) {
                unsigned long long aa = packdup(av[i]);
                ffma2(acc[i][0], aa, b.x);
                ffma2(acc[i][1], aa, b.y);
            }
        }
        if (more) {
            int nxt = cur ^ 1;
            #pragma unroll
            for (int q = 0; q < 4; q++) {
                As[nxt][ak + q][arow]     = ((const float*)&pa0)[q];
                As[nxt][ak + 8 + q][arow] = ((const float*)&pa1)[q];
                Bs[nxt][bk + q][brow]     = ((const float*)&pb)[q];
            }
            __syncthreads();
            cur = nxt;
        }
    }

    #pragma unroll
    for (int i = 0; i < 8; i++) {
        float2 p0 = unpack2(acc[i][0]);
        float2 p1 = unpack2(acc[i][1]);
        float* dst = out + (long)(by*128 + ty*8 + i)*1024 + bx*64 + tx*4;
        *(float4*)dst = make_float4(p0.x, p0.y, p1.x, p1.y);
    }
}

// ---------------------------------------------------------------------------
extern "C" void kernel_launch(void* const* d_in, const int* in_sizes, int n_in,
                              void* d_out, int out_size) {
    const float* xf  = (const float*)d_in[0];  // person_features [8,20,16,1024]
    const float* Wh  = (const float*)d_in[1];  // W_hidden [1024,1024]
    const float* w1  = (const float*)d_in[2];  // p_w1 [18,1024,3,3]
    const float* bb1 = (const float*)d_in[3];  // p_b1 [18]
    const float* w2  = (const float*)d_in[4];  // p_w2 [18,1024,3,3]
    const float* bb2 = (const float*)d_in[5];  // p_b2 [18]
    (void)in_sizes; (void)n_in;

    float* out       = (float*)d_out;
    float* out_dyn   = out;                       // [2560,1024]
    float* out_ftmad = out + (long)NPOS * TC;     // [2560,9,1024]
    int write_ftmad  = (out_size >= NPOS*TC + NPOS*9*TC) ? 1 : 0;

    k_wtrans<<<(2*9*1024*18 + 255)/256, 256>>>(w1, w2);

    dim3 gconv(80, 6);
    k_conv<<<gconv, 192>>>(xf);

    k_gather<<<NPOS, 256>>>(xf, bb1, bb2, out_ftmad, write_ftmad);

    dim3 ggemm(16, 20);
    k_gemm<<<ggemm, 256>>>(Wh, out_dyn);
}

// round 5
// speedup vs baseline: 1.6530x; 1.3557x over previous
#include <cuda_runtime.h>
#include <cuda_bf16.h>
#include <cstdint>

// Problem constants
#define TB   8
#define TT   20
#define TN   16
#define TC   1024
#define NPOS 2560          // B*T*N
#define NO   18            // 2*K2

// Scratch (allocation-free rule: __device__ globals)
__device__ float g_wT[2*9*1024*18];            // conv weights transposed
__device__ float g_offp[3*2*NPOS*NO];          // conv partial sums
__device__ __nv_bfloat16 g_ahi[NPOS*TC];       // A hi (from gather)
__device__ __nv_bfloat16 g_alo[NPOS*TC];       // A lo
__device__ __nv_bfloat16 g_bhi[1024*1024];     // W hi
__device__ __nv_bfloat16 g_blo[1024*1024];     // W lo

__device__ __forceinline__ uint32_t smem_u32(const void* p) {
    uint32_t a;
    asm("{ .reg .u64 t; cvta.to.shared.u64 t, %1; cvt.u32.u64 %0, t; }"
        : "=r"(a) : "l"(p));
    return a;
}

#define LDM4(r, addr) \
    asm volatile("ldmatrix.sync.aligned.m8n8.x4.shared.b16 {%0,%1,%2,%3}, [%4];" \
        : "=r"((r)[0]), "=r"((r)[1]), "=r"((r)[2]), "=r"((r)[3]) : "r"(addr))
#define LDM2(r, addr) \
    asm volatile("ldmatrix.sync.aligned.m8n8.x2.shared.b16 {%0,%1}, [%2];" \
        : "=r"((r)[0]), "=r"((r)[1]) : "r"(addr))

__device__ __forceinline__ void mma_bf16(float* d, const uint32_t* a, const uint32_t* b) {
    asm volatile("mma.sync.aligned.m16n8k16.row.col.f32.bf16.bf16.f32 "
                 "{%0,%1,%2,%3}, {%4,%5,%6,%7}, {%8,%9}, {%0,%1,%2,%3};"
                 : "+f"(d[0]), "+f"(d[1]), "+f"(d[2]), "+f"(d[3])
                 : "r"(a[0]), "r"(a[1]), "r"(a[2]), "r"(a[3]), "r"(b[0]), "r"(b[1]));
}

// ---------------------------------------------------------------------------
// Kernel 1: conv weight transpose  p_w [18][1024][3][3] -> g_wT [r][tap][c][18]
// ---------------------------------------------------------------------------
__global__ void k_wtrans(const float* __restrict__ w1, const float* __restrict__ w2) {
    int idx = blockIdx.x * 256 + threadIdx.x;
    if (idx >= 2*9*1024*18) return;
    int o   = idx % 18;
    int c   = (idx / 18) % 1024;
    int tap = (idx / (18*1024)) % 9;
    int r   = idx / (18*1024*9);
    const float* w = r ? w2 : w1;
    g_wT[idx] = w[o*9216 + c*9 + tap];
}

// ---------------------------------------------------------------------------
// Kernel 1b: W_hidden -> bf16 hi/lo split
// ---------------------------------------------------------------------------
union BPack { __nv_bfloat162 h2[2]; uint2 u; };

__global__ void k_wprep(const float* __restrict__ W) {
    int idx = blockIdx.x * 256 + threadIdx.x;     // one per 4 floats
    if (idx >= 1024*1024/4) return;
    float4 v = *(const float4*)(W + idx*4);
    BPack ph, pl;
    __nv_bfloat16 h;
    h = __float2bfloat16(v.x); ph.h2[0].x = h; pl.h2[0].x = __float2bfloat16(v.x - __bfloat162float(h));
    h = __float2bfloat16(v.y); ph.h2[0].y = h; pl.h2[0].y = __float2bfloat16(v.y - __bfloat162float(h));
    h = __float2bfloat16(v.z); ph.h2[1].x = h; pl.h2[1].x = __float2bfloat16(v.z - __bfloat162float(h));
    h = __float2bfloat16(v.w); ph.h2[1].y = h; pl.h2[1].y = __float2bfloat16(v.w - __bfloat162float(h));
    *(uint2*)(g_bhi + idx*4) = ph.u;
    *(uint2*)(g_blo + idx*4) = pl.u;
}

// ---------------------------------------------------------------------------
// Kernel 2: offset conv (unchanged)
// ---------------------------------------------------------------------------
__global__ void __launch_bounds__(192) k_conv(const float* __restrict__ x) {
    int tile = blockIdx.x;
    int rz   = blockIdx.y;
    int r    = rz / 3;
    int tg   = rz - r*3;
    int ratio = r + 1;

    __shared__ float Xs[32][33];
    __shared__ float Ws[576];

    int tid  = threadIdx.x;
    int w    = tid >> 5;
    int lane = tid & 31;
    int posg = tile*32 + lane;

    float acc0 = 0.f, acc1 = 0.f, acc2 = 0.f;

    for (int ti = 0; ti < 3; ti++) {
        int tap = tg*3 + ti;
        int kh  = tap/3 - 1;
        int kw  = tap%3 - 1;

        const float* rp[6];
        #pragma unroll
        for (int s = 0; s < 6; s++) {
            int idx = tid + s*192;
            rp[s] = nullptr;
            if (idx < 1024) {
                int pp = idx >> 5, cc = idx & 31;
                int pg = tile*32 + pp;
                int bb = pg / 320; int rem = pg - bb*320;
                int t  = rem >> 4, n = rem & 15;
                int st = t + kh*ratio, sn = n + kw*ratio;
                if ((unsigned)st < (unsigned)TT && (unsigned)sn < (unsigned)TN)
                    rp[s] = x + (((bb*TT + st)*TN + sn)*TC + cc);
            }
        }

        const float* wbase = g_wT + (r*9 + tap)*1024*18;

        for (int c0 = 0; c0 < 1024; c0 += 32) {
            __syncthreads();
            #pragma unroll
            for (int s = 0; s < 6; s++) {
                int idx = tid + s*192;
                if (idx < 1024)
                    Xs[idx & 31][idx >> 5] = rp[s] ? __ldg(rp[s] + c0) : 0.f;
            }
            #pragma unroll
            for (int s = 0; s < 3; s++) {
                int idx = tid + s*192;
                Ws[idx] = wbase[c0*18 + idx];
            }
            __syncthreads();
            #pragma unroll
            for (int cc = 0; cc < 32; cc++) {
                float xv = Xs[cc][lane];
                acc0 = fmaf(xv, Ws[cc*18 + w],      acc0);
                acc1 = fmaf(xv, Ws[cc*18 + w + 6],  acc1);
                acc2 = fmaf(xv, Ws[cc*18 + w + 12], acc2);
            }
        }
    }

    float* dst = g_offp + ((tg*2 + r)*NPOS + posg)*NO;
    dst[w]      = acc0;
    dst[w + 6]  = acc1;
    dst[w + 12] = acc2;
}

// ---------------------------------------------------------------------------
// Kernel 3: deformable bilinear gather; epilogue writes A in bf16 hi/lo
// ---------------------------------------------------------------------------
__global__ void __launch_bounds__(256) k_gather(const float* __restrict__ x,
                                                const float* __restrict__ b1,
                                                const float* __restrict__ b2,
                                                float* __restrict__ out_ftmad,
                                                int write_ftmad) {
    int pos = blockIdx.x;
    int bb  = pos / 320; int rem = pos - bb*320;
    int t   = rem >> 4,  n = rem & 15;

    __shared__ int   s_off[2][9][4];
    __shared__ float s_coe[2][9][4];

    int tid = threadIdx.x;
    if (tid < 18) {
        int r = tid / 9, k = tid - r*9;
        int ratio = r + 1;
        const float* bias = r ? b2 : b1;
        float offt = bias[k], offn = bias[k + 9];
        #pragma unroll
        for (int tg = 0; tg < 3; tg++) {
            const float* op = g_offp + ((tg*2 + r)*NPOS + pos)*NO;
            offt += op[k];
            offn += op[k + 9];
        }
        float Tp1 = (float)(TT + 2*ratio - 1);
        float Np1 = (float)(TN + 2*ratio - 1);
        float post = (float)(t + ratio) + (float)((k/3 - 1)*ratio) + offt;
        float posn = (float)(n + ratio) + (float)((k%3 - 1)*ratio) + offn;
        float flt = floorf(post), fln = floorf(posn);
        float ltt = fminf(fmaxf(flt,       0.f), Tp1);
        float ltn = fminf(fmaxf(fln,       0.f), Np1);
        float rbt = fminf(fmaxf(flt + 1.f, 0.f), Tp1);
        float rbn = fminf(fmaxf(fln + 1.f, 0.f), Np1);
        float pct = fminf(fmaxf(post, 0.f), Tp1);
        float pcn = fminf(fmaxf(posn, 0.f), Np1);
        float wltt = 1.f - fabsf(pct - ltt);
        float wrbt = 1.f - fabsf(pct - rbt);
        float wltn = 1.f - fabsf(pcn - ltn);
        float wrbn = 1.f - fabsf(pcn - rbn);
        s_coe[r][k][0] = wltt * wltn;
        s_coe[r][k][1] = wrbt * wrbn;
        s_coe[r][k][2] = wrbt * wltn;
        s_coe[r][k][3] = wltt * wrbn;
        int ict[4] = {(int)ltt, (int)rbt, (int)rbt, (int)ltt};
        int icn[4] = {(int)ltn, (int)rbn, (int)ltn, (int)rbn};
        #pragma unroll
        for (int q = 0; q < 4; q++) {
            int ts = ict[q] - ratio, ns = icn[q] - ratio;
            s_off[r][k][q] = ((unsigned)ts < (unsigned)TT && (unsigned)ns < (unsigned)TN)
                           ? ((bb*TT + ts)*TN + ns)*TC : -1;
        }
    }
    __syncthreads();

    int c = tid * 4;
    float dx = 0.f, dy = 0.f, dz = 0.f, dw = 0.f;
    #pragma unroll
    for (int r = 0; r < 2; r++) {
        #pragma unroll
        for (int k = 0; k < 9; k++) {
            float fx = 0.f, fy = 0.f, fz = 0.f, fw = 0.f;
            #pragma unroll
            for (int q = 0; q < 4; q++) {
                int   o   = s_off[r][k][q];
                float coe = s_coe[r][k][q];
                if (o >= 0) {
                    float4 v = *(const float4*)(x + o + c);
                    fx = fmaf(coe, v.x, fx);
                    fy = fmaf(coe, v.y, fy);
                    fz = fmaf(coe, v.z, fz);
                    fw = fmaf(coe, v.w, fw);
                }
            }
            if (r == 1 && write_ftmad) {
                float4 ov = make_float4(fx, fy, fz, fw);
                *(float4*)(out_ftmad + (pos*9 + k)*1024 + c) = ov;
            }
            dx += fx; dy += fy; dz += fz; dw += fw;
        }
    }
    const float s = 1.f / 18.f;
    float4 dv = make_float4(dx*s, dy*s, dz*s, dw*s);

    // bf16 hi/lo split of A for the tensor-core GEMM
    BPack ph, pl;
    __nv_bfloat16 h;
    h = __float2bfloat16(dv.x); ph.h2[0].x = h; pl.h2[0].x = __float2bfloat16(dv.x - __bfloat162float(h));
    h = __float2bfloat16(dv.y); ph.h2[0].y = h; pl.h2[0].y = __float2bfloat16(dv.y - __bfloat162float(h));
    h = __float2bfloat16(dv.z); ph.h2[1].x = h; pl.h2[1].x = __float2bfloat16(dv.z - __bfloat162float(h));
    h = __float2bfloat16(dv.w); ph.h2[1].y = h; pl.h2[1].y = __float2bfloat16(dv.w - __bfloat162float(h));
    *(uint2*)(g_ahi + (long)pos*1024 + c) = ph.u;
    *(uint2*)(g_alo + (long)pos*1024 + c) = pl.u;
}

// ---------------------------------------------------------------------------
// Kernel 4: HMMA (mma.sync m16n8k16 bf16) split GEMM  out[2560,1024] = A @ W^T
// CTA tile M128 x N64, 8 warps (4x2), warp tile 32x32.
// K-slab 32, double-buffered SMEM, 80B row stride (conflict-free ldmatrix).
// D += Ahi*Bhi + Ahi*Blo + Alo*Bhi  (fp32 accumulators)
// ---------------------------------------------------------------------------
#define KC       32
#define NSLAB    (1024/KC)
#define SA       80                    // bytes per smem row (32 bf16 + 16B pad)
#define S_AHI    0
#define S_ALO    (128*SA)              // 10240
#define S_BHI    (2*128*SA)            // 20480
#define S_BLO    (2*128*SA + 64*SA)    // 25600
#define STG      (2*128*SA + 2*64*SA)  // 30720 per buffer
#define GSMEM    (2*STG)               // 61440

__global__ void __launch_bounds__(256, 2) k_gemm_mma(float* __restrict__ out) {
    extern __shared__ __align__(16) char smem[];
    const uint32_t sb = smem_u32(smem);

    const int tid  = threadIdx.x;
    const int wid  = tid >> 5;
    const int lane = tid & 31;
    const int bx   = blockIdx.x;      // N tile of 64 (0..15)
    const int by   = blockIdx.y;      // M tile of 128 (0..19)
    const int wy   = wid & 3;         // warp m quadrant (32 rows)
    const int wx   = wid >> 2;        // warp n half (32 cols)

    const __nv_bfloat16* pAhi = g_ahi + (long)by*128*1024;
    const __nv_bfloat16* pAlo = g_alo + (long)by*128*1024;
    const __nv_bfloat16* pBhi = g_bhi + (long)bx*64*1024;
    const __nv_bfloat16* pBlo = g_blo + (long)bx*64*1024;

    // loaders: A rows (tid>>2) and (tid>>2)+64, chunk (tid&3); B row tid>>2
    const int lrow = tid >> 2, lc4 = tid & 3;
    const long ga0 = (long)lrow*1024 + lc4*8;
    const long ga1 = (long)(lrow+64)*1024 + lc4*8;
    const uint32_t sa0 = (uint32_t)(lrow*SA + lc4*16);
    const uint32_t sa1 = (uint32_t)((lrow+64)*SA + lc4*16);

    float acc[2][4][4];
    #pragma unroll
    for (int i = 0; i < 2; i++)
        #pragma unroll
        for (int j = 0; j < 4; j++)
            #pragma unroll
            for (int q = 0; q < 4; q++) acc[i][j][q] = 0.f;

    // ldmatrix lane-address components
    const uint32_t laneA = (uint32_t)((lane & 15)*SA + (lane >> 4)*16);
    const uint32_t laneB = (uint32_t)((lane & 7)*SA + ((lane >> 3) & 1)*16);

    // preload slab 0 into buffer 0
    uint4 ra0 = *(const uint4*)(pAhi + ga0);
    uint4 ra1 = *(const uint4*)(pAhi + ga1);
    uint4 ra2 = *(const uint4*)(pAlo + ga0);
    uint4 ra3 = *(const uint4*)(pAlo + ga1);
    uint4 rb0 = *(const uint4*)(pBhi + ga0);
    uint4 rb1 = *(const uint4*)(pBlo + ga0);
    {
        uint32_t base = sb;
        *(uint4*)(smem + (base - sb) + S_AHI + sa0) = ra0;
        *(uint4*)(smem + (base - sb) + S_AHI + sa1) = ra1;
        *(uint4*)(smem + (base - sb) + S_ALO + sa0) = ra2;
        *(uint4*)(smem + (base - sb) + S_ALO + sa1) = ra3;
        *(uint4*)(smem + (base - sb) + S_BHI + sa0) = rb0;
        *(uint4*)(smem + (base - sb) + S_BLO + sa0) = rb1;
    }
    __syncthreads();

    int cur = 0;
    for (int s = 1; s <= NSLAB; s++) {
        bool more = (s < NSLAB);
        if (more) {
            long k0 = (long)s * KC;
            ra0 = *(const uint4*)(pAhi + ga0 + k0);
            ra1 = *(const uint4*)(pAhi + ga1 + k0);
            ra2 = *(const uint4*)(pAlo + ga0 + k0);
            ra3 = *(const uint4*)(pAlo + ga1 + k0);
            rb0 = *(const uint4*)(pBhi + ga0 + k0);
            rb1 = *(const uint4*)(pBlo + ga0 + k0);
        }

        // compute on buffer `cur`
        uint32_t base = sb + cur*STG;
        #pragma unroll
        for (int kk = 0; kk < 2; kk++) {           // two k16 steps per slab
            uint32_t kB = kk * 32;                 // 16 bf16 = 32 bytes
            uint32_t ah[2][4], al[2][4], bh[4][2], bl[4][2];
            #pragma unroll
            for (int mi = 0; mi < 2; mi++) {
                uint32_t moff = (uint32_t)((wy*32 + mi*16)*SA) + kB + laneA;
                LDM4(ah[mi], base + S_AHI + moff);
                LDM4(al[mi], base + S_ALO + moff);
            }
            #pragma unroll
            for (int ni = 0; ni < 4; ni++) {
                uint32_t noff = (uint32_t)((wx*32 + ni*8)*SA) + kB + laneB;
                LDM2(bh[ni], base + S_BHI + noff);
                LDM2(bl[ni], base + S_BLO + noff);
            }
            #pragma unroll
            for (int mi = 0; mi < 2; mi++)
                #pragma unroll
                for (int ni = 0; ni < 4; ni++) {
                    mma_bf16(acc[mi][ni], ah[mi], bh[ni]);
                    mma_bf16(acc[mi][ni], ah[mi], bl[ni]);
                    mma_bf16(acc[mi][ni], al[mi], bh[ni]);
                }
        }

        if (more) {
            int nxt = cur ^ 1;
            char* nb = smem + nxt*STG;
            *(uint4*)(nb + S_AHI + sa0) = ra0;
            *(uint4*)(nb + S_AHI + sa1) = ra1;
            *(uint4*)(nb + S_ALO + sa0) = ra2;
            *(uint4*)(nb + S_ALO + sa1) = ra3;
            *(uint4*)(nb + S_BHI + sa0) = rb0;
            *(uint4*)(nb + S_BLO + sa0) = rb1;
            __syncthreads();
            cur = nxt;
        }
    }

    // epilogue: D frag thread mapping (m16n8): d0,d1 -> row l/4, cols (l%4)*2,+1;
    // d2,d3 -> row l/4+8
    const int r0 = (lane >> 2);
    const int c0 = (lane & 3) * 2;
    #pragma unroll
    for (int mi = 0; mi < 2; mi++) {
        #pragma unroll
        for (int ni = 0; ni < 4; ni++) {
            long row = (long)by*128 + wy*32 + mi*16 + r0;
            long col = (long)bx*64 + wx*32 + ni*8 + c0;
            *(float2*)(out + row*1024 + col)       = make_float2(acc[mi][ni][0], acc[mi][ni][1]);
            *(float2*)(out + (row + 8)*1024 + col) = make_float2(acc[mi][ni][2], acc[mi][ni][3]);
        }
    }
}

// ---------------------------------------------------------------------------
extern "C" void kernel_launch(void* const* d_in, const int* in_sizes, int n_in,
                              void* d_out, int out_size) {
    const float* xf  = (const float*)d_in[0];  // person_features [8,20,16,1024]
    const float* Wh  = (const float*)d_in[1];  // W_hidden [1024,1024]
    const float* w1  = (const float*)d_in[2];  // p_w1 [18,1024,3,3]
    const float* bb1 = (const float*)d_in[3];  // p_b1 [18]
    const float* w2  = (const float*)d_in[4];  // p_w2 [18,1024,3,3]
    const float* bb2 = (const float*)d_in[5];  // p_b2 [18]
    (void)in_sizes; (void)n_in;

    float* out       = (float*)d_out;
    float* out_dyn   = out;                       // [2560,1024]
    float* out_ftmad = out + (long)NPOS * TC;     // [2560,9,1024]
    int write_ftmad  = (out_size >= NPOS*TC + NPOS*9*TC) ? 1 : 0;

    cudaFuncSetAttribute(k_gemm_mma, cudaFuncAttributeMaxDynamicSharedMemorySize,
                         GSMEM);

    k_wtrans<<<(2*9*1024*18 + 255)/256, 256>>>(w1, w2);
    k_wprep<<<1024, 256>>>(Wh);

    dim3 gconv(80, 6);
    k_conv<<<gconv, 192>>>(xf);

    k_gather<<<NPOS, 256>>>(xf, bb1, bb2, out_ftmad, write_ftmad);

    dim3 ggemm(16, 20);
    k_gemm_mma<<<ggemm, 256, GSMEM>>>(out_dyn);
}

// round 6
// speedup vs baseline: 2.0396x; 1.2339x over previous
#include <cuda_runtime.h>
#include <cuda_bf16.h>
#include <cstdint>

typedef unsigned long long ull;

// Problem constants
#define TB   8
#define TT   20
#define TN   16
#define TC   1024
#define NPOS 2560          // B*T*N
#define NO   18            // 2*K2

// Scratch (allocation-free rule: __device__ globals)
__device__ float2 g_wTp[2*9*512*18];           // conv weights, channel-paired
__device__ float g_offp[3*2*NPOS*NO];          // conv partial sums
__device__ __nv_bfloat16 g_ahi[NPOS*TC];       // A hi (from gather)
__device__ __nv_bfloat16 g_alo[NPOS*TC];       // A lo
__device__ __nv_bfloat16 g_bhi[1024*1024];     // W hi
__device__ __nv_bfloat16 g_blo[1024*1024];     // W lo

__device__ __forceinline__ uint32_t smem_u32(const void* p) {
    uint32_t a;
    asm("{ .reg .u64 t; cvta.to.shared.u64 t, %1; cvt.u32.u64 %0, t; }"
        : "=r"(a) : "l"(p));
    return a;
}

// ---- packed fp32x2 helpers --------------------------------------------------
__device__ __forceinline__ void ffma2(ull& acc, ull a, ull b) {
    asm("fma.rn.f32x2 %0, %1, %2, %0;" : "+l"(acc) : "l"(a), "l"(b));
}
__device__ __forceinline__ float2 unpack2(ull v) {
    float2 r;
    asm("mov.b64 {%0, %1}, %2;" : "=f"(r.x), "=f"(r.y) : "l"(v));
    return r;
}

#define LDM4(r, addr) \
    asm volatile("ldmatrix.sync.aligned.m8n8.x4.shared.b16 {%0,%1,%2,%3}, [%4];" \
        : "=r"((r)[0]), "=r"((r)[1]), "=r"((r)[2]), "=r"((r)[3]) : "r"(addr))
#define LDM2(r, addr) \
    asm volatile("ldmatrix.sync.aligned.m8n8.x2.shared.b16 {%0,%1}, [%2];" \
        : "=r"((r)[0]), "=r"((r)[1]) : "r"(addr))

__device__ __forceinline__ void mma_bf16(float* d, const uint32_t* a, const uint32_t* b) {
    asm volatile("mma.sync.aligned.m16n8k16.row.col.f32.bf16.bf16.f32 "
                 "{%0,%1,%2,%3}, {%4,%5,%6,%7}, {%8,%9}, {%0,%1,%2,%3};"
                 : "+f"(d[0]), "+f"(d[1]), "+f"(d[2]), "+f"(d[3])
                 : "r"(a[0]), "r"(a[1]), "r"(a[2]), "r"(a[3]), "r"(b[0]), "r"(b[1]));
}

// ---------------------------------------------------------------------------
// Kernel 1: conv weight prep  p_w [18][1024][3][3] -> g_wTp [r][tap][c2][18] f2
// pair = (w[o][2c2][tap], w[o][2c2+1][tap])
// ---------------------------------------------------------------------------
__global__ void k_wtrans(const float* __restrict__ w1, const float* __restrict__ w2) {
    int idx = blockIdx.x * 256 + threadIdx.x;
    if (idx >= 2*9*512*18) return;
    int o   = idx % 18;
    int c2  = (idx / 18) % 512;
    int tap = (idx / (18*512)) % 9;
    int r   = idx / (18*512*9);
    const float* w = r ? w2 : w1;
    float2 v;
    v.x = w[o*9216 + (2*c2)*9 + tap];
    v.y = w[o*9216 + (2*c2+1)*9 + tap];
    g_wTp[idx] = v;
}

// ---------------------------------------------------------------------------
// Kernel 1b: W_hidden -> bf16 hi/lo split
// ---------------------------------------------------------------------------
union BPack { __nv_bfloat162 h2[2]; uint2 u; };

__global__ void k_wprep(const float* __restrict__ W) {
    int idx = blockIdx.x * 256 + threadIdx.x;     // one per 4 floats
    if (idx >= 1024*1024/4) return;
    float4 v = *(const float4*)(W + idx*4);
    BPack ph, pl;
    __nv_bfloat16 h;
    h = __float2bfloat16(v.x); ph.h2[0].x = h; pl.h2[0].x = __float2bfloat16(v.x - __bfloat162float(h));
    h = __float2bfloat16(v.y); ph.h2[0].y = h; pl.h2[0].y = __float2bfloat16(v.y - __bfloat162float(h));
    h = __float2bfloat16(v.z); ph.h2[1].x = h; pl.h2[1].x = __float2bfloat16(v.z - __bfloat162float(h));
    h = __float2bfloat16(v.w); ph.h2[1].y = h; pl.h2[1].y = __float2bfloat16(v.w - __bfloat162float(h));
    *(uint2*)(g_bhi + idx*4) = ph.u;
    *(uint2*)(g_blo + idx*4) = pl.u;
}

// ---------------------------------------------------------------------------
// Kernel 2: offset conv, FFMA2 channel-paired + register double-buffering.
// grid = (80 pos-tiles of 32) x (2 ratios * 3 tapgroups), block 192 = 6 warps.
// warp w -> outputs {w, w+6, w+12}; lane <-> position.
// 96 iterations (3 taps x 32 channel-chunks of 32ch = 16 c2).
// ---------------------------------------------------------------------------
__global__ void __launch_bounds__(192) k_conv(const float* __restrict__ x) {
    int tile = blockIdx.x;           // 0..79
    int rz   = blockIdx.y;           // 0..5
    int r    = rz / 3;
    int tg   = rz - r*3;
    int ratio = r + 1;

    __shared__ float2 Xs[2][16][33]; // [buf][c2][pos] (pad 33)
    __shared__ float2 Ws[2][288];    // [buf][c2*18 + o]

    int tid  = threadIdx.x;
    int w    = tid >> 5;
    int lane = tid & 31;
    int posg = tile*32 + lane;

    // row pointers per tap (3) per X slot (3); slot idx = tid + s*192 (<512)
    const float* rp[3][3];
    #pragma unroll
    for (int ti = 0; ti < 3; ti++) {
        int tap = tg*3 + ti;
        int kh  = tap/3 - 1;
        int kw  = tap%3 - 1;
        #pragma unroll
        for (int s = 0; s < 3; s++) {
            int idx = tid + s*192;
            rp[ti][s] = nullptr;
            if (idx < 512) {
                int pp = idx >> 4, c2 = idx & 15;
                int pg = tile*32 + pp;
                int bb = pg / 320; int rem = pg - bb*320;
                int t  = rem >> 4, n = rem & 15;
                int st = t + kh*ratio, sn = n + kw*ratio;
                if ((unsigned)st < (unsigned)TT && (unsigned)sn < (unsigned)TN)
                    rp[ti][s] = x + (((bb*TT + st)*TN + sn)*TC) + c2*2;
            }
        }
    }
    const float2* wbase = g_wTp + (size_t)(r*9 + tg*3)*512*18;

    float2 px[3], pw[2];

    // ---- prefetch helpers (manually inlined via macros) ----
#define CONV_LOAD(it) do { \
        int _tap = (it) >> 5, _ch = (it) & 31; \
        _Pragma("unroll") \
        for (int s = 0; s < 3; s++) { \
            const float* p = rp[_tap][s]; \
            px[s] = p ? *(const float2*)(p + _ch*32) : make_float2(0.f, 0.f); \
        } \
        const float2* wb = wbase + (size_t)_tap*512*18 + _ch*288; \
        _Pragma("unroll") \
        for (int s = 0; s < 2; s++) { \
            int idx = tid + s*192; \
            pw[s] = (idx < 288) ? wb[idx] : make_float2(0.f, 0.f); \
        } \
    } while (0)

#define CONV_STORE(buf) do { \
        _Pragma("unroll") \
        for (int s = 0; s < 3; s++) { \
            int idx = tid + s*192; \
            if (idx < 512) Xs[buf][idx & 15][idx >> 4] = px[s]; \
        } \
        _Pragma("unroll") \
        for (int s = 0; s < 2; s++) { \
            int idx = tid + s*192; \
            if (idx < 288) Ws[buf][idx] = pw[s]; \
        } \
    } while (0)

    ull acc0 = 0ULL, acc1 = 0ULL, acc2 = 0ULL;

    CONV_LOAD(0);
    CONV_STORE(0);
    __syncthreads();

    for (int it = 0; it < 96; it++) {
        int buf = it & 1;
        if (it < 95) CONV_LOAD(it + 1);       // global loads overlap compute
        #pragma unroll
        for (int c2 = 0; c2 < 16; c2++) {
            ull xp = *(const ull*)&Xs[buf][c2][lane];
            const ull* wrow = (const ull*)&Ws[buf][c2*18];
            ffma2(acc0, xp, wrow[w]);
            ffma2(acc1, xp, wrow[w + 6]);
            ffma2(acc2, xp, wrow[w + 12]);
        }
        if (it < 95) {
            __syncthreads();
            CONV_STORE(buf ^ 1);
            __syncthreads();
        }
    }

    float2 a0 = unpack2(acc0), a1 = unpack2(acc1), a2 = unpack2(acc2);
    float* dst = g_offp + ((tg*2 + r)*NPOS + posg)*NO;
    dst[w]      = a0.x + a0.y;
    dst[w + 6]  = a1.x + a1.y;
    dst[w + 12] = a2.x + a2.y;
#undef CONV_LOAD
#undef CONV_STORE
}

// ---------------------------------------------------------------------------
// Kernel 3: deformable bilinear gather; epilogue writes A in bf16 hi/lo
// ---------------------------------------------------------------------------
__global__ void __launch_bounds__(256) k_gather(const float* __restrict__ x,
                                                const float* __restrict__ b1,
                                                const float* __restrict__ b2,
                                                float* __restrict__ out_ftmad,
                                                int write_ftmad) {
    int pos = blockIdx.x;
    int bb  = pos / 320; int rem = pos - bb*320;
    int t   = rem >> 4,  n = rem & 15;

    __shared__ int   s_off[2][9][4];
    __shared__ float s_coe[2][9][4];

    int tid = threadIdx.x;
    if (tid < 18) {
        int r = tid / 9, k = tid - r*9;
        int ratio = r + 1;
        const float* bias = r ? b2 : b1;
        float offt = bias[k], offn = bias[k + 9];
        #pragma unroll
        for (int tg = 0; tg < 3; tg++) {
            const float* op = g_offp + ((tg*2 + r)*NPOS + pos)*NO;
            offt += op[k];
            offn += op[k + 9];
        }
        float Tp1 = (float)(TT + 2*ratio - 1);
        float Np1 = (float)(TN + 2*ratio - 1);
        float post = (float)(t + ratio) + (float)((k/3 - 1)*ratio) + offt;
        float posn = (float)(n + ratio) + (float)((k%3 - 1)*ratio) + offn;
        float flt = floorf(post), fln = floorf(posn);
        float ltt = fminf(fmaxf(flt,       0.f), Tp1);
        float ltn = fminf(fmaxf(fln,       0.f), Np1);
        float rbt = fminf(fmaxf(flt + 1.f, 0.f), Tp1);
        float rbn = fminf(fmaxf(fln + 1.f, 0.f), Np1);
        float pct = fminf(fmaxf(post, 0.f), Tp1);
        float pcn = fminf(fmaxf(posn, 0.f), Np1);
        float wltt = 1.f - fabsf(pct - ltt);
        float wrbt = 1.f - fabsf(pct - rbt);
        float wltn = 1.f - fabsf(pcn - ltn);
        float wrbn = 1.f - fabsf(pcn - rbn);
        s_coe[r][k][0] = wltt * wltn;
        s_coe[r][k][1] = wrbt * wrbn;
        s_coe[r][k][2] = wrbt * wltn;
        s_coe[r][k][3] = wltt * wrbn;
        int ict[4] = {(int)ltt, (int)rbt, (int)rbt, (int)ltt};
        int icn[4] = {(int)ltn, (int)rbn, (int)ltn, (int)rbn};
        #pragma unroll
        for (int q = 0; q < 4; q++) {
            int ts = ict[q] - ratio, ns = icn[q] - ratio;
            s_off[r][k][q] = ((unsigned)ts < (unsigned)TT && (unsigned)ns < (unsigned)TN)
                           ? ((bb*TT + ts)*TN + ns)*TC : -1;
        }
    }
    __syncthreads();

    int c = tid * 4;
    float dx = 0.f, dy = 0.f, dz = 0.f, dw = 0.f;
    #pragma unroll
    for (int r = 0; r < 2; r++) {
        #pragma unroll
        for (int k = 0; k < 9; k++) {
            float fx = 0.f, fy = 0.f, fz = 0.f, fw = 0.f;
            #pragma unroll
            for (int q = 0; q < 4; q++) {
                int   o   = s_off[r][k][q];
                float coe = s_coe[r][k][q];
                if (o >= 0) {
                    float4 v = *(const float4*)(x + o + c);
                    fx = fmaf(coe, v.x, fx);
                    fy = fmaf(coe, v.y, fy);
                    fz = fmaf(coe, v.z, fz);
                    fw = fmaf(coe, v.w, fw);
                }
            }
            if (r == 1 && write_ftmad) {
                float4 ov = make_float4(fx, fy, fz, fw);
                *(float4*)(out_ftmad + (pos*9 + k)*1024 + c) = ov;
            }
            dx += fx; dy += fy; dz += fz; dw += fw;
        }
    }
    const float s = 1.f / 18.f;
    float4 dv = make_float4(dx*s, dy*s, dz*s, dw*s);

    // bf16 hi/lo split of A for the tensor-core GEMM
    BPack ph, pl;
    __nv_bfloat16 h;
    h = __float2bfloat16(dv.x); ph.h2[0].x = h; pl.h2[0].x = __float2bfloat16(dv.x - __bfloat162float(h));
    h = __float2bfloat16(dv.y); ph.h2[0].y = h; pl.h2[0].y = __float2bfloat16(dv.y - __bfloat162float(h));
    h = __float2bfloat16(dv.z); ph.h2[1].x = h; pl.h2[1].x = __float2bfloat16(dv.z - __bfloat162float(h));
    h = __float2bfloat16(dv.w); ph.h2[1].y = h; pl.h2[1].y = __float2bfloat16(dv.w - __bfloat162float(h));
    *(uint2*)(g_ahi + (long)pos*1024 + c) = ph.u;
    *(uint2*)(g_alo + (long)pos*1024 + c) = pl.u;
}

// ---------------------------------------------------------------------------
// Kernel 4: HMMA (mma.sync m16n8k16 bf16) split GEMM  out[2560,1024] = A @ W^T
// CTA tile M128 x N64, 8 warps (4x2), warp tile 32x32.
// K-slab 32, double-buffered SMEM, 80B row stride (conflict-free ldmatrix).
// D += Ahi*Bhi + Ahi*Blo + Alo*Bhi  (fp32 accumulators)
// ---------------------------------------------------------------------------
#define KC       32
#define NSLAB    (1024/KC)
#define SA       80                    // bytes per smem row (32 bf16 + 16B pad)
#define S_AHI    0
#define S_ALO    (128*SA)              // 10240
#define S_BHI    (2*128*SA)            // 20480
#define S_BLO    (2*128*SA + 64*SA)    // 25600
#define STG      (2*128*SA + 2*64*SA)  // 30720 per buffer
#define GSMEM    (2*STG)               // 61440

__global__ void __launch_bounds__(256, 2) k_gemm_mma(float* __restrict__ out) {
    extern __shared__ __align__(16) char smem[];
    const uint32_t sb = smem_u32(smem);

    const int tid  = threadIdx.x;
    const int wid  = tid >> 5;
    const int lane = tid & 31;
    const int bx   = blockIdx.x;      // N tile of 64 (0..15)
    const int by   = blockIdx.y;      // M tile of 128 (0..19)
    const int wy   = wid & 3;         // warp m quadrant (32 rows)
    const int wx   = wid >> 2;        // warp n half (32 cols)

    const __nv_bfloat16* pAhi = g_ahi + (long)by*128*1024;
    const __nv_bfloat16* pAlo = g_alo + (long)by*128*1024;
    const __nv_bfloat16* pBhi = g_bhi + (long)bx*64*1024;
    const __nv_bfloat16* pBlo = g_blo + (long)bx*64*1024;

    const int lrow = tid >> 2, lc4 = tid & 3;
    const long ga0 = (long)lrow*1024 + lc4*8;
    const long ga1 = (long)(lrow+64)*1024 + lc4*8;
    const uint32_t sa0 = (uint32_t)(lrow*SA + lc4*16);
    const uint32_t sa1 = (uint32_t)((lrow+64)*SA + lc4*16);

    float acc[2][4][4];
    #pragma unroll
    for (int i = 0; i < 2; i++)
        #pragma unroll
        for (int j = 0; j < 4; j++)
            #pragma unroll
            for (int q = 0; q < 4; q++) acc[i][j][q] = 0.f;

    const uint32_t laneA = (uint32_t)((lane & 15)*SA + (lane >> 4)*16);
    const uint32_t laneB = (uint32_t)((lane & 7)*SA + ((lane >> 3) & 1)*16);

    uint4 ra0 = *(const uint4*)(pAhi + ga0);
    uint4 ra1 = *(const uint4*)(pAhi + ga1);
    uint4 ra2 = *(const uint4*)(pAlo + ga0);
    uint4 ra3 = *(const uint4*)(pAlo + ga1);
    uint4 rb0 = *(const uint4*)(pBhi + ga0);
    uint4 rb1 = *(const uint4*)(pBlo + ga0);
    {
        *(uint4*)(smem + S_AHI + sa0) = ra0;
        *(uint4*)(smem + S_AHI + sa1) = ra1;
        *(uint4*)(smem + S_ALO + sa0) = ra2;
        *(uint4*)(smem + S_ALO + sa1) = ra3;
        *(uint4*)(smem + S_BHI + sa0) = rb0;
        *(uint4*)(smem + S_BLO + sa0) = rb1;
    }
    __syncthreads();

    int cur = 0;
    for (int s = 1; s <= NSLAB; s++) {
        bool more = (s < NSLAB);
        if (more) {
            long k0 = (long)s * KC;
            ra0 = *(const uint4*)(pAhi + ga0 + k0);
            ra1 = *(const uint4*)(pAhi + ga1 + k0);
            ra2 = *(const uint4*)(pAlo + ga0 + k0);
            ra3 = *(const uint4*)(pAlo + ga1 + k0);
            rb0 = *(const uint4*)(pBhi + ga0 + k0);
            rb1 = *(const uint4*)(pBlo + ga0 + k0);
        }

        uint32_t base = sb + cur*STG;
        #pragma unroll
        for (int kk = 0; kk < 2; kk++) {
            uint32_t kB = kk * 32;
            uint32_t ah[2][4], al[2][4], bh[4][2], bl[4][2];
            #pragma unroll
            for (int mi = 0; mi < 2; mi++) {
                uint32_t moff = (uint32_t)((wy*32 + mi*16)*SA) + kB + laneA;
                LDM4(ah[mi], base + S_AHI + moff);
                LDM4(al[mi], base + S_ALO + moff);
            }
            #pragma unroll
            for (int ni = 0; ni < 4; ni++) {
                uint32_t noff = (uint32_t)((wx*32 + ni*8)*SA) + kB + laneB;
                LDM2(bh[ni], base + S_BHI + noff);
                LDM2(bl[ni], base + S_BLO + noff);
            }
            #pragma unroll
            for (int mi = 0; mi < 2; mi++)
                #pragma unroll
                for (int ni = 0; ni < 4; ni++) {
                    mma_bf16(acc[mi][ni], ah[mi], bh[ni]);
                    mma_bf16(acc[mi][ni], ah[mi], bl[ni]);
                    mma_bf16(acc[mi][ni], al[mi], bh[ni]);
                }
        }

        if (more) {
            int nxt = cur ^ 1;
            char* nb = smem + nxt*STG;
            *(uint4*)(nb + S_AHI + sa0) = ra0;
            *(uint4*)(nb + S_AHI + sa1) = ra1;
            *(uint4*)(nb + S_ALO + sa0) = ra2;
            *(uint4*)(nb + S_ALO + sa1) = ra3;
            *(uint4*)(nb + S_BHI + sa0) = rb0;
            *(uint4*)(nb + S_BLO + sa0) = rb1;
            __syncthreads();
            cur = nxt;
        }
    }

    const int r0 = (lane >> 2);
    const int c0 = (lane & 3) * 2;
    #pragma unroll
    for (int mi = 0; mi < 2; mi++) {
        #pragma unroll
        for (int ni = 0; ni < 4; ni++) {
            long row = (long)by*128 + wy*32 + mi*16 + r0;
            long col = (long)bx*64 + wx*32 + ni*8 + c0;
            *(float2*)(out + row*1024 + col)       = make_float2(acc[mi][ni][0], acc[mi][ni][1]);
            *(float2*)(out + (row + 8)*1024 + col) = make_float2(acc[mi][ni][2], acc[mi][ni][3]);
        }
    }
}

// ---------------------------------------------------------------------------
extern "C" void kernel_launch(void* const* d_in, const int* in_sizes, int n_in,
                              void* d_out, int out_size) {
    const float* xf  = (const float*)d_in[0];  // person_features [8,20,16,1024]
    const float* Wh  = (const float*)d_in[1];  // W_hidden [1024,1024]
    const float* w1  = (const float*)d_in[2];  // p_w1 [18,1024,3,3]
    const float* bb1 = (const float*)d_in[3];  // p_b1 [18]
    const float* w2  = (const float*)d_in[4];  // p_w2 [18,1024,3,3]
    const float* bb2 = (const float*)d_in[5];  // p_b2 [18]
    (void)in_sizes; (void)n_in;

    float* out       = (float*)d_out;
    float* out_dyn   = out;                       // [2560,1024]
    float* out_ftmad = out + (long)NPOS * TC;     // [2560,9,1024]
    int write_ftmad  = (out_size >= NPOS*TC + NPOS*9*TC) ? 1 : 0;

    cudaFuncSetAttribute(k_gemm_mma, cudaFuncAttributeMaxDynamicSharedMemorySize,
                         GSMEM);

    k_wtrans<<<(2*9*512*18 + 255)/256, 256>>>(w1, w2);
    k_wprep<<<1024, 256>>>(Wh);

    dim3 gconv(80, 6);
    k_conv<<<gconv, 192>>>(xf);

    k_gather<<<NPOS, 256>>>(xf, bb1, bb2, out_ftmad, write_ftmad);

    dim3 ggemm(16, 20);
    k_gemm_mma<<<ggemm, 256, GSMEM>>>(out_dyn);
}

// round 7
// speedup vs baseline: 2.1164x; 1.0376x over previous
#include <cuda_runtime.h>
#include <cuda_bf16.h>
#include <cstdint>

typedef unsigned long long ull;

// Problem constants
#define TB   8
#define TT   20
#define TN   16
#define TC   1024
#define NPOS 2560          // B*T*N
#define NO   18            // 2*K2

// Scratch (allocation-free rule: __device__ globals)
__device__ float2 g_wTp[2*9*512*18];           // conv weights, channel-paired
__device__ float g_offp[4*2*NPOS*NO];          // conv partial sums (4 c-quarters)
__device__ __nv_bfloat16 g_ahi[NPOS*TC];       // A hi (from gather)
__device__ __nv_bfloat16 g_alo[NPOS*TC];       // A lo
__device__ __nv_bfloat16 g_bhi[1024*1024];     // W hi
__device__ __nv_bfloat16 g_blo[1024*1024];     // W lo

__device__ __forceinline__ uint32_t smem_u32(const void* p) {
    uint32_t a;
    asm("{ .reg .u64 t; cvta.to.shared.u64 t, %1; cvt.u32.u64 %0, t; }"
        : "=r"(a) : "l"(p));
    return a;
}

// ---- packed fp32x2 helpers ------------------------------------------------
__device__ __forceinline__ void ffma2(ull& acc, ull a, ull b) {
    asm("fma.rn.f32x2 %0, %1, %2, %0;" : "+l"(acc) : "l"(a), "l"(b));
}
__device__ __forceinline__ float2 unpack2(ull v) {
    float2 r;
    asm("mov.b64 {%0, %1}, %2;" : "=f"(r.x), "=f"(r.y) : "l"(v));
    return r;
}
__device__ __forceinline__ ull lds64(uint32_t a) {
    ull v;
    asm volatile("ld.shared.b64 %0, [%1];" : "=l"(v) : "r"(a));
    return v;
}
__device__ __forceinline__ void cp_async8(uint32_t dst, const void* src) {
    asm volatile("cp.async.ca.shared.global [%0], [%1], 8;" :: "r"(dst), "l"(src));
}
#define CP_COMMIT() asm volatile("cp.async.commit_group;" ::: "memory")
#define CP_WAIT0()  asm volatile("cp.async.wait_group 0;" ::: "memory")

#define LDM4(r, addr) \
    asm volatile("ldmatrix.sync.aligned.m8n8.x4.shared.b16 {%0,%1,%2,%3}, [%4];" \
        : "=r"((r)[0]), "=r"((r)[1]), "=r"((r)[2]), "=r"((r)[3]) : "r"(addr))
#define LDM2(r, addr) \
    asm volatile("ldmatrix.sync.aligned.m8n8.x2.shared.b16 {%0,%1}, [%2];" \
        : "=r"((r)[0]), "=r"((r)[1]) : "r"(addr))

__device__ __forceinline__ void mma_bf16(float* d, const uint32_t* a, const uint32_t* b) {
    asm volatile("mma.sync.aligned.m16n8k16.row.col.f32.bf16.bf16.f32 "
                 "{%0,%1,%2,%3}, {%4,%5,%6,%7}, {%8,%9}, {%0,%1,%2,%3};"
                 : "+f"(d[0]), "+f"(d[1]), "+f"(d[2]), "+f"(d[3])
                 : "r"(a[0]), "r"(a[1]), "r"(a[2]), "r"(a[3]), "r"(b[0]), "r"(b[1]));
}

// ---------------------------------------------------------------------------
// Kernel 1: conv weight prep  p_w [18][1024][3][3] -> g_wTp [r][tap][c2][18] f2
// ---------------------------------------------------------------------------
__global__ void k_wtrans(const float* __restrict__ w1, const float* __restrict__ w2) {
    int idx = blockIdx.x * 256 + threadIdx.x;
    if (idx >= 2*9*512*18) return;
    int o   = idx % 18;
    int c2  = (idx / 18) % 512;
    int tap = (idx / (18*512)) % 9;
    int r   = idx / (18*512*9);
    const float* w = r ? w2 : w1;
    float2 v;
    v.x = w[o*9216 + (2*c2)*9 + tap];
    v.y = w[o*9216 + (2*c2+1)*9 + tap];
    g_wTp[idx] = v;
}

// ---------------------------------------------------------------------------
// Kernel 1b: W_hidden -> bf16 hi/lo split
// ---------------------------------------------------------------------------
union BPack { __nv_bfloat162 h2[2]; uint2 u; };

__global__ void k_wprep(const float* __restrict__ W) {
    int idx = blockIdx.x * 256 + threadIdx.x;     // one per 4 floats
    if (idx >= 1024*1024/4) return;
    float4 v = *(const float4*)(W + idx*4);
    BPack ph, pl;
    __nv_bfloat16 h;
    h = __float2bfloat16(v.x); ph.h2[0].x = h; pl.h2[0].x = __float2bfloat16(v.x - __bfloat162float(h));
    h = __float2bfloat16(v.y); ph.h2[0].y = h; pl.h2[0].y = __float2bfloat16(v.y - __bfloat162float(h));
    h = __float2bfloat16(v.z); ph.h2[1].x = h; pl.h2[1].x = __float2bfloat16(v.z - __bfloat162float(h));
    h = __float2bfloat16(v.w); ph.h2[1].y = h; pl.h2[1].y = __float2bfloat16(v.w - __bfloat162float(h));
    *(uint2*)(g_bhi + idx*4) = ph.u;
    *(uint2*)(g_blo + idx*4) = pl.u;
}

// ---------------------------------------------------------------------------
// Kernel 2: offset conv — fused all (ratio,tap); cp.async double-buffered.
// grid = (80 pos-tiles of 32) x (4 channel-quarters), block 192 = 6 warps.
// Per CTA: zero-padded X halo tile [c2][6 t'][20 n'] per 16-ch chunk (8 c2),
// weights [18 rtap][8 c2][18 o]. 16 chunks, 1 barrier each.
// warp w -> outputs {w, w+6, w+12} per ratio; lane <-> position.
// ---------------------------------------------------------------------------
#define CONV_XF2   960                 // 8 c2 * 120 rows
#define CONV_WF2   2592                // 18 * 8 * 18
#define CONV_SMEM  ((2*CONV_XF2 + 2*CONV_WF2) * 8)   // 56832 B

__global__ void __launch_bounds__(192) k_conv(const float* __restrict__ x) {
    extern __shared__ __align__(16) float2 cs[];
    const uint32_t sbase = smem_u32(cs);
    const uint32_t sX = sbase;                          // 2 x 960 f2
    const uint32_t sW = sbase + 2*CONV_XF2*8;           // 2 x 2592 f2

    const int tile = blockIdx.x;      // 0..79
    const int cq   = blockIdx.y;      // 0..3
    const int b    = tile / 10;
    const int t0   = (tile - b*10) * 2;

    const int tid   = threadIdx.x;
    const int w     = tid >> 5;
    const int lane  = tid & 31;
    const int tlane = lane >> 4;
    const int nlane = lane & 15;
    const int posg  = tile*32 + lane;

    // ---- zero X buffers (halo stays zero forever) ----
    for (int i = tid; i < 2*CONV_XF2; i += 192)
        cs[i] = make_float2(0.f, 0.f);

    // ---- per-thread loader slots (chunk-invariant) ----
    // X: 4 slots, idx = tid + s*192 < 768 : c2 = idx&7, row = idx>>3,
    //    t' = row>>4, n' = 2 + (row&15)
    const float* xsrc[4];
    uint32_t     xdst[4];
    #pragma unroll
    for (int s = 0; s < 4; s++) {
        int idx = tid + s*192;
        int c2 = idx & 7, row = idx >> 3;
        int tp = row >> 4, np = row & 15;
        int tsrc = t0 + tp - 2;
        xdst[s] = (uint32_t)((c2*120 + tp*20 + np + 2) * 8);
        xsrc[s] = ((unsigned)tsrc < (unsigned)TT)
                ? x + ((size_t)((b*TT + tsrc)*TN + np))*TC + cq*256 + c2*2
                : nullptr;
    }
    // W: 14 slots, idx = tid + s*192 < 2592 : o = idx%18, c2 = (idx/18)%8,
    //    rtap = idx/144 ; src f2 = (rtap*512 + cq*128 + c2)*18 + o
    uint32_t wsrc[14];
    #pragma unroll
    for (int s = 0; s < 14; s++) {
        int idx = tid + s*192;
        if (idx < CONV_WF2) {
            int o = idx % 18;
            int q = idx / 18;
            int c2 = q & 7;
            int rtap = idx / 144;
            wsrc[s] = (uint32_t)((rtap*512 + cq*128 + c2)*18 + o);
        } else wsrc[s] = 0xFFFFFFFFu;
    }

    __syncthreads();   // zeros visible before cp.async writes

#define CONV_ISSUE(chunk, buf) do { \
        const float* _xb = x ? (const float*)0 : (const float*)0; (void)_xb; \
        _Pragma("unroll") \
        for (int s = 0; s < 4; s++) \
            if (xsrc[s]) cp_async8(sX + (uint32_t)(buf)*CONV_XF2*8 + xdst[s], \
                                   xsrc[s] + (chunk)*16); \
        const float2* _wg = g_wTp + (size_t)(chunk)*144; \
        _Pragma("unroll") \
        for (int s = 0; s < 14; s++) \
            if (wsrc[s] != 0xFFFFFFFFu) \
                cp_async8(sW + (uint32_t)(buf)*CONV_WF2*8 + (uint32_t)(tid + s*192)*8, \
                          _wg + wsrc[s]); \
        CP_COMMIT(); \
    } while (0)

    CONV_ISSUE(0, 0);

    ull acc[2][3];
    #pragma unroll
    for (int r = 0; r < 2; r++)
        #pragma unroll
        for (int j = 0; j < 3; j++) acc[r][j] = 0ULL;

    for (int chunk = 0; chunk < 16; chunk++) {
        int buf = chunk & 1;
        CP_WAIT0();
        __syncthreads();
        if (chunk < 15) CONV_ISSUE(chunk + 1, buf ^ 1);

        uint32_t xbB = sX + (uint32_t)buf*CONV_XF2*8;
        uint32_t wbB = sW + (uint32_t)buf*CONV_WF2*8 + (uint32_t)w*8;
        #pragma unroll
        for (int rtap = 0; rtap < 18; rtap++) {
            const int r = rtap / 9, tap = rtap - r*9, ratio = r + 1;
            const int dt = (tap/3 - 1) * ratio, dn = (tap%3 - 1) * ratio;
            uint32_t xa = xbB + (uint32_t)(((tlane + dt + 2)*20 + (nlane + dn + 2)) * 8);
            uint32_t wa = wbB + (uint32_t)(rtap * 144 * 8);
            #pragma unroll
            for (int c2 = 0; c2 < 8; c2++) {
                ull xp = lds64(xa + c2*960);
                ffma2(acc[r][0], xp, lds64(wa + c2*144));
                ffma2(acc[r][1], xp, lds64(wa + c2*144 + 48));
                ffma2(acc[r][2], xp, lds64(wa + c2*144 + 96));
            }
        }
    }

    #pragma unroll
    for (int r = 0; r < 2; r++) {
        float* dst = g_offp + ((size_t)(cq*2 + r)*NPOS + posg)*NO;
        #pragma unroll
        for (int j = 0; j < 3; j++) {
            float2 v = unpack2(acc[r][j]);
            dst[w + j*6] = v.x + v.y;
        }
    }
#undef CONV_ISSUE
}

// ---------------------------------------------------------------------------
// Kernel 3: deformable bilinear gather; epilogue writes A in bf16 hi/lo
// ---------------------------------------------------------------------------
__global__ void __launch_bounds__(256) k_gather(const float* __restrict__ x,
                                                const float* __restrict__ b1,
                                                const float* __restrict__ b2,
                                                float* __restrict__ out_ftmad,
                                                int write_ftmad) {
    int pos = blockIdx.x;
    int bb  = pos / 320; int rem = pos - bb*320;
    int t   = rem >> 4,  n = rem & 15;

    __shared__ int   s_off[2][9][4];
    __shared__ float s_coe[2][9][4];

    int tid = threadIdx.x;
    if (tid < 18) {
        int r = tid / 9, k = tid - r*9;
        int ratio = r + 1;
        const float* bias = r ? b2 : b1;
        float offt = bias[k], offn = bias[k + 9];
        #pragma unroll
        for (int q = 0; q < 4; q++) {
            const float* op = g_offp + ((size_t)(q*2 + r)*NPOS + pos)*NO;
            offt += op[k];
            offn += op[k + 9];
        }
        float Tp1 = (float)(TT + 2*ratio - 1);
        float Np1 = (float)(TN + 2*ratio - 1);
        float post = (float)(t + ratio) + (float)((k/3 - 1)*ratio) + offt;
        float posn = (float)(n + ratio) + (float)((k%3 - 1)*ratio) + offn;
        float flt = floorf(post), fln = floorf(posn);
        float ltt = fminf(fmaxf(flt,       0.f), Tp1);
        float ltn = fminf(fmaxf(fln,       0.f), Np1);
        float rbt = fminf(fmaxf(flt + 1.f, 0.f), Tp1);
        float rbn = fminf(fmaxf(fln + 1.f, 0.f), Np1);
        float pct = fminf(fmaxf(post, 0.f), Tp1);
        float pcn = fminf(fmaxf(posn, 0.f), Np1);
        float wltt = 1.f - fabsf(pct - ltt);
        float wrbt = 1.f - fabsf(pct - rbt);
        float wltn = 1.f - fabsf(pcn - ltn);
        float wrbn = 1.f - fabsf(pcn - rbn);
        s_coe[r][k][0] = wltt * wltn;
        s_coe[r][k][1] = wrbt * wrbn;
        s_coe[r][k][2] = wrbt * wltn;
        s_coe[r][k][3] = wltt * wrbn;
        int ict[4] = {(int)ltt, (int)rbt, (int)rbt, (int)ltt};
        int icn[4] = {(int)ltn, (int)rbn, (int)ltn, (int)rbn};
        #pragma unroll
        for (int q = 0; q < 4; q++) {
            int ts = ict[q] - ratio, ns = icn[q] - ratio;
            s_off[r][k][q] = ((unsigned)ts < (unsigned)TT && (unsigned)ns < (unsigned)TN)
                           ? ((bb*TT + ts)*TN + ns)*TC : -1;
        }
    }
    __syncthreads();

    int c = tid * 4;
    float dx = 0.f, dy = 0.f, dz = 0.f, dw = 0.f;
    #pragma unroll
    for (int r = 0; r < 2; r++) {
        #pragma unroll
        for (int k = 0; k < 9; k++) {
            float fx = 0.f, fy = 0.f, fz = 0.f, fw = 0.f;
            #pragma unroll
            for (int q = 0; q < 4; q++) {
                int   o   = s_off[r][k][q];
                float coe = s_coe[r][k][q];
                if (o >= 0) {
                    float4 v = *(const float4*)(x + o + c);
                    fx = fmaf(coe, v.x, fx);
                    fy = fmaf(coe, v.y, fy);
                    fz = fmaf(coe, v.z, fz);
                    fw = fmaf(coe, v.w, fw);
                }
            }
            if (r == 1 && write_ftmad) {
                float4 ov = make_float4(fx, fy, fz, fw);
                *(float4*)(out_ftmad + (pos*9 + k)*1024 + c) = ov;
            }
            dx += fx; dy += fy; dz += fz; dw += fw;
        }
    }
    const float s = 1.f / 18.f;
    float4 dv = make_float4(dx*s, dy*s, dz*s, dw*s);

    BPack ph, pl;
    __nv_bfloat16 h;
    h = __float2bfloat16(dv.x); ph.h2[0].x = h; pl.h2[0].x = __float2bfloat16(dv.x - __bfloat162float(h));
    h = __float2bfloat16(dv.y); ph.h2[0].y = h; pl.h2[0].y = __float2bfloat16(dv.y - __bfloat162float(h));
    h = __float2bfloat16(dv.z); ph.h2[1].x = h; pl.h2[1].x = __float2bfloat16(dv.z - __bfloat162float(h));
    h = __float2bfloat16(dv.w); ph.h2[1].y = h; pl.h2[1].y = __float2bfloat16(dv.w - __bfloat162float(h));
    *(uint2*)(g_ahi + (long)pos*1024 + c) = ph.u;
    *(uint2*)(g_alo + (long)pos*1024 + c) = pl.u;
}

// ---------------------------------------------------------------------------
// Kernel 4: HMMA (mma.sync m16n8k16 bf16) split GEMM  out[2560,1024] = A @ W^T
// ---------------------------------------------------------------------------
#define KC       32
#define NSLAB    (1024/KC)
#define SA       80
#define S_AHI    0
#define S_ALO    (128*SA)
#define S_BHI    (2*128*SA)
#define S_BLO    (2*128*SA + 64*SA)
#define STG      (2*128*SA + 2*64*SA)
#define GSMEM    (2*STG)

__global__ void __launch_bounds__(256, 2) k_gemm_mma(float* __restrict__ out) {
    extern __shared__ __align__(16) char smem[];
    const uint32_t sb = smem_u32(smem);

    const int tid  = threadIdx.x;
    const int wid  = tid >> 5;
    const int lane = tid & 31;
    const int bx   = blockIdx.x;
    const int by   = blockIdx.y;
    const int wy   = wid & 3;
    const int wx   = wid >> 2;

    const __nv_bfloat16* pAhi = g_ahi + (long)by*128*1024;
    const __nv_bfloat16* pAlo = g_alo + (long)by*128*1024;
    const __nv_bfloat16* pBhi = g_bhi + (long)bx*64*1024;
    const __nv_bfloat16* pBlo = g_blo + (long)bx*64*1024;

    const int lrow = tid >> 2, lc4 = tid & 3;
    const long ga0 = (long)lrow*1024 + lc4*8;
    const long ga1 = (long)(lrow+64)*1024 + lc4*8;
    const uint32_t sa0 = (uint32_t)(lrow*SA + lc4*16);
    const uint32_t sa1 = (uint32_t)((lrow+64)*SA + lc4*16);

    float acc[2][4][4];
    #pragma unroll
    for (int i = 0; i < 2; i++)
        #pragma unroll
        for (int j = 0; j < 4; j++)
            #pragma unroll
            for (int q = 0; q < 4; q++) acc[i][j][q] = 0.f;

    const uint32_t laneA = (uint32_t)((lane & 15)*SA + (lane >> 4)*16);
    const uint32_t laneB = (uint32_t)((lane & 7)*SA + ((lane >> 3) & 1)*16);

    uint4 ra0 = *(const uint4*)(pAhi + ga0);
    uint4 ra1 = *(const uint4*)(pAhi + ga1);
    uint4 ra2 = *(const uint4*)(pAlo + ga0);
    uint4 ra3 = *(const uint4*)(pAlo + ga1);
    uint4 rb0 = *(const uint4*)(pBhi + ga0);
    uint4 rb1 = *(const uint4*)(pBlo + ga0);
    {
        *(uint4*)(smem + S_AHI + sa0) = ra0;
        *(uint4*)(smem + S_AHI + sa1) = ra1;
        *(uint4*)(smem + S_ALO + sa0) = ra2;
        *(uint4*)(smem + S_ALO + sa1) = ra3;
        *(uint4*)(smem + S_BHI + sa0) = rb0;
        *(uint4*)(smem + S_BLO + sa0) = rb1;
    }
    __syncthreads();

    int cur = 0;
    for (int s = 1; s <= NSLAB; s++) {
        bool more = (s < NSLAB);
        if (more) {
            long k0 = (long)s * KC;
            ra0 = *(const uint4*)(pAhi + ga0 + k0);
            ra1 = *(const uint4*)(pAhi + ga1 + k0);
            ra2 = *(const uint4*)(pAlo + ga0 + k0);
            ra3 = *(const uint4*)(pAlo + ga1 + k0);
            rb0 = *(const uint4*)(pBhi + ga0 + k0);
            rb1 = *(const uint4*)(pBlo + ga0 + k0);
        }

        uint32_t base = sb + cur*STG;
        #pragma unroll
        for (int kk = 0; kk < 2; kk++) {
            uint32_t kB = kk * 32;
            uint32_t ah[2][4], al[2][4], bh[4][2], bl[4][2];
            #pragma unroll
            for (int mi = 0; mi < 2; mi++) {
                uint32_t moff = (uint32_t)((wy*32 + mi*16)*SA) + kB + laneA;
                LDM4(ah[mi], base + S_AHI + moff);
                LDM4(al[mi], base + S_ALO + moff);
            }
            #pragma unroll
            for (int ni = 0; ni < 4; ni++) {
                uint32_t noff = (uint32_t)((wx*32 + ni*8)*SA) + kB + laneB;
                LDM2(bh[ni], base + S_BHI + noff);
                LDM2(bl[ni], base + S_BLO + noff);
            }
            #pragma unroll
            for (int mi = 0; mi < 2; mi++)
                #pragma unroll
                for (int ni = 0; ni < 4; ni++) {
                    mma_bf16(acc[mi][ni], ah[mi], bh[ni]);
                    mma_bf16(acc[mi][ni], ah[mi], bl[ni]);
                    mma_bf16(acc[mi][ni], al[mi], bh[ni]);
                }
        }

        if (more) {
            int nxt = cur ^ 1;
            char* nb = smem + nxt*STG;
            *(uint4*)(nb + S_AHI + sa0) = ra0;
            *(uint4*)(nb + S_AHI + sa1) = ra1;
            *(uint4*)(nb + S_ALO + sa0) = ra2;
            *(uint4*)(nb + S_ALO + sa1) = ra3;
            *(uint4*)(nb + S_BHI + sa0) = rb0;
            *(uint4*)(nb + S_BLO + sa0) = rb1;
            __syncthreads();
            cur = nxt;
        }
    }

    const int r0 = (lane >> 2);
    const int c0 = (lane & 3) * 2;
    #pragma unroll
    for (int mi = 0; mi < 2; mi++) {
        #pragma unroll
        for (int ni = 0; ni < 4; ni++) {
            long row = (long)by*128 + wy*32 + mi*16 + r0;
            long col = (long)bx*64 + wx*32 + ni*8 + c0;
            *(float2*)(out + row*1024 + col)       = make_float2(acc[mi][ni][0], acc[mi][ni][1]);
            *(float2*)(out + (row + 8)*1024 + col) = make_float2(acc[mi][ni][2], acc[mi][ni][3]);
        }
    }
}

// ---------------------------------------------------------------------------
extern "C" void kernel_launch(void* const* d_in, const int* in_sizes, int n_in,
                              void* d_out, int out_size) {
    const float* xf  = (const float*)d_in[0];  // person_features [8,20,16,1024]
    const float* Wh  = (const float*)d_in[1];  // W_hidden [1024,1024]
    const float* w1  = (const float*)d_in[2];  // p_w1 [18,1024,3,3]
    const float* bb1 = (const float*)d_in[3];  // p_b1 [18]
    const float* w2  = (const float*)d_in[4];  // p_w2 [18,1024,3,3]
    const float* bb2 = (const float*)d_in[5];  // p_b2 [18]
    (void)in_sizes; (void)n_in;

    float* out       = (float*)d_out;
    float* out_dyn   = out;                       // [2560,1024]
    float* out_ftmad = out + (long)NPOS * TC;     // [2560,9,1024]
    int write_ftmad  = (out_size >= NPOS*TC + NPOS*9*TC) ? 1 : 0;

    cudaFuncSetAttribute(k_gemm_mma, cudaFuncAttributeMaxDynamicSharedMemorySize,
                         GSMEM);
    cudaFuncSetAttribute(k_conv, cudaFuncAttributeMaxDynamicSharedMemorySize,
                         CONV_SMEM);

    k_wtrans<<<(2*9*512*18 + 255)/256, 256>>>(w1, w2);
    k_wprep<<<1024, 256>>>(Wh);

    dim3 gconv(80, 4);
    k_conv<<<gconv, 192, CONV_SMEM>>>(xf);

    k_gather<<<NPOS, 256>>>(xf, bb1, bb2, out_ftmad, write_ftmad);

    dim3 ggemm(16, 20);
    k_gemm_mma<<<ggemm, 256, GSMEM>>>(out_dyn);
}

// round 8
// speedup vs baseline: 2.4774x; 1.1706x over previous
#include <cuda_runtime.h>
#include <cuda_bf16.h>
#include <cstdint>

typedef unsigned long long ull;

// Problem constants
#define TB   8
#define TT   20
#define TN   16
#define TC   1024
#define NPOS 2560          // B*T*N
#define NO   18            // 2*K2

// Scratch (allocation-free rule: __device__ globals)
__device__ __align__(16) float2 g_wTp[2*9*512*18];  // conv weights, channel-paired
__device__ float g_offp[64*NPOS*18];           // conv partials: 32 c-slices x 2 ratios
__device__ __nv_bfloat16 g_ahi[NPOS*TC];       // A hi (from gather)
__device__ __nv_bfloat16 g_alo[NPOS*TC];       // A lo
__device__ __nv_bfloat16 g_bhi[1024*1024];     // W hi
__device__ __nv_bfloat16 g_blo[1024*1024];     // W lo

__device__ __forceinline__ uint32_t smem_u32(const void* p) {
    uint32_t a;
    asm("{ .reg .u64 t; cvta.to.shared.u64 t, %1; cvt.u32.u64 %0, t; }"
        : "=r"(a) : "l"(p));
    return a;
}

// ---- packed fp32x2 helpers ------------------------------------------------
__device__ __forceinline__ void ffma2(ull& acc, ull a, ull b) {
    asm("fma.rn.f32x2 %0, %1, %2, %0;" : "+l"(acc) : "l"(a), "l"(b));
}
__device__ __forceinline__ float2 unpack2(ull v) {
    float2 r;
    asm("mov.b64 {%0, %1}, %2;" : "=f"(r.x), "=f"(r.y) : "l"(v));
    return r;
}
__device__ __forceinline__ ull lds64(uint32_t a) {
    ull v;
    asm volatile("ld.shared.b64 %0, [%1];" : "=l"(v) : "r"(a));
    return v;
}
__device__ __forceinline__ void lds128u64(ull& w0, ull& w1, uint32_t a) {
    asm volatile("ld.shared.v2.u64 {%0,%1}, [%2];" : "=l"(w0), "=l"(w1) : "r"(a));
}
__device__ __forceinline__ void cp_async8(uint32_t dst, const void* src) {
    asm volatile("cp.async.ca.shared.global [%0], [%1], 8;" :: "r"(dst), "l"(src));
}
__device__ __forceinline__ void cp_async16(uint32_t dst, const void* src) {
    asm volatile("cp.async.ca.shared.global [%0], [%1], 16;" :: "r"(dst), "l"(src));
}
#define CP_COMMIT() asm volatile("cp.async.commit_group;" ::: "memory")
#define CP_WAIT0()  asm volatile("cp.async.wait_group 0;" ::: "memory")

#define LDM4(r, addr) \
    asm volatile("ldmatrix.sync.aligned.m8n8.x4.shared.b16 {%0,%1,%2,%3}, [%4];" \
        : "=r"((r)[0]), "=r"((r)[1]), "=r"((r)[2]), "=r"((r)[3]) : "r"(addr))
#define LDM2(r, addr) \
    asm volatile("ldmatrix.sync.aligned.m8n8.x2.shared.b16 {%0,%1}, [%2];" \
        : "=r"((r)[0]), "=r"((r)[1]) : "r"(addr))

__device__ __forceinline__ void mma_bf16(float* d, const uint32_t* a, const uint32_t* b) {
    asm volatile("mma.sync.aligned.m16n8k16.row.col.f32.bf16.bf16.f32 "
                 "{%0,%1,%2,%3}, {%4,%5,%6,%7}, {%8,%9}, {%0,%1,%2,%3};"
                 : "+f"(d[0]), "+f"(d[1]), "+f"(d[2]), "+f"(d[3])
                 : "r"(a[0]), "r"(a[1]), "r"(a[2]), "r"(a[3]), "r"(b[0]), "r"(b[1]));
}

// ---------------------------------------------------------------------------
// Kernel 1: conv weight prep  p_w [18][1024][3][3] -> g_wTp [rtap][c2][18] f2
// ---------------------------------------------------------------------------
__global__ void k_wtrans(const float* __restrict__ w1, const float* __restrict__ w2) {
    int idx = blockIdx.x * 256 + threadIdx.x;
    if (idx >= 2*9*512*18) return;
    int o   = idx % 18;
    int c2  = (idx / 18) % 512;
    int tap = (idx / (18*512)) % 9;
    int r   = idx / (18*512*9);
    const float* w = r ? w2 : w1;
    float2 v;
    v.x = w[o*9216 + (2*c2)*9 + tap];
    v.y = w[o*9216 + (2*c2+1)*9 + tap];
    g_wTp[idx] = v;
}

// ---------------------------------------------------------------------------
// Kernel 1b: W_hidden -> bf16 hi/lo split
// ---------------------------------------------------------------------------
union BPack { __nv_bfloat162 h2[2]; uint2 u; };

__global__ void k_wprep(const float* __restrict__ W) {
    int idx = blockIdx.x * 256 + threadIdx.x;     // one per 4 floats
    if (idx >= 1024*1024/4) return;
    float4 v = *(const float4*)(W + idx*4);
    BPack ph, pl;
    __nv_bfloat16 h;
    h = __float2bfloat16(v.x); ph.h2[0].x = h; pl.h2[0].x = __float2bfloat16(v.x - __bfloat162float(h));
    h = __float2bfloat16(v.y); ph.h2[0].y = h; pl.h2[0].y = __float2bfloat16(v.y - __bfloat162float(h));
    h = __float2bfloat16(v.z); ph.h2[1].x = h; pl.h2[1].x = __float2bfloat16(v.z - __bfloat162float(h));
    h = __float2bfloat16(v.w); ph.h2[1].y = h; pl.h2[1].y = __float2bfloat16(v.w - __bfloat162float(h));
    *(uint2*)(g_bhi + idx*4) = ph.u;
    *(uint2*)(g_blo + idx*4) = pl.u;
}

// ---------------------------------------------------------------------------
// Kernel 2: offset conv v3 — register-blocked (P=2 pos x O=18 out per thread).
// grid = (40 pos-tiles of 64) x (8 channel-eighths of 64 c2), block 256.
// 8 warps = 2 ratios x 4 c-slices (16 c2 each). Chunks of 8 c2 (2 per slice),
// 8 chunks, cp.async double-buffered, 1 barrier per chunk.
// X tile: [8 c2][8 t'][20 n'] f2 (zero halo); W: [18 rtap][8 c2][18 o] f2.
// Thread: lane -> (tl,nl); positions (t0+tl, nl) and (t0+tl+2, nl).
// Per (tap,c2): 2 X LDS.64 + 9 W LDS.128(broadcast) + 36 FFMA2.
// ---------------------------------------------------------------------------
#define CV_XBUF 1280                 // f2: 8 c2 * 160 rows
#define CV_WBUF 2592                 // f2: 18 * 8 * 18
#define CV_SMEM ((2*CV_XBUF + 2*CV_WBUF) * 8)   // 61952 B

__global__ void __launch_bounds__(256, 2) k_conv(const float* __restrict__ x) {
    extern __shared__ __align__(16) float2 cs[];
    const uint32_t sb  = smem_u32(cs);
    const uint32_t sX0 = sb;
    const uint32_t sX1 = sb + CV_XBUF*8;
    const uint32_t sW0 = sb + 2*CV_XBUF*8;
    const uint32_t sW1 = sW0 + CV_WBUF*8;

    const int tile = blockIdx.x;      // 0..39 = b*5 + tq
    const int e    = blockIdx.y;      // 0..7 channel-eighth
    const int b    = tile / 5;
    const int t0   = (tile - b*5) * 4;

    const int tid  = threadIdx.x;
    const int wid  = tid >> 5, lane = tid & 31;
    const int r    = wid >> 2;        // ratio index (0,1)
    const int s    = wid & 3;         // c-slice within eighth
    const int ratio = r + 1;
    const int tl = lane >> 4, nl = lane & 15;

    // zero X buffers once (halo slots never overwritten -> stay zero)
    for (int i = tid; i < 2*CV_XBUF; i += 256) cs[i] = make_float2(0.f, 0.f);

    // ---- loader slots (chunk ck advances src by fixed byte step) ----
    // X: idx = tid + k*256 < 1280 : c2i = idx&7, row = idx>>3
    uint32_t xoff[5], xdst[5];
    #pragma unroll
    for (int k = 0; k < 5; k++) {
        int idx = tid + k*256;
        int c2i = idx & 7, row = idx >> 3;
        int t = t0 + row/20 - 2, n = row%20 - 2;
        int c2 = e*64 + (c2i>>1)*16 + (c2i&1);
        xdst[k] = (uint32_t)((c2i*160 + row)*8);
        xoff[k] = (t >= 0 && t < TT && n >= 0 && n < TN)
                ? (uint32_t)((((b*TT + t)*TN + n)*TC + c2*2) * 4)
                : 0xFFFFFFFFu;
    }
    // W: idx < 1296 : o2 = idx%9, c2i = (idx/9)&7, rtap = idx/72
    uint32_t woff[6], wdst[6];
    #pragma unroll
    for (int k = 0; k < 6; k++) {
        int idx = tid + k*256;
        if (idx < 1296) {
            int o2 = idx % 9, c2i = (idx/9) & 7, rtap = idx / 72;
            int c2 = e*64 + (c2i>>1)*16 + (c2i&1);
            wdst[k] = (uint32_t)((((rtap*8 + c2i)*18) + o2*2) * 8);
            woff[k] = (uint32_t)((((rtap*512 + c2)*18) + o2*2) * 8);
        } else woff[k] = 0xFFFFFFFFu;
    }
    const char* xb = (const char*)x;
    const char* wb = (const char*)g_wTp;

    __syncthreads();   // zeros visible before async writes

#define CV_ISSUE(ck, bX, bW) do { \
        _Pragma("unroll") \
        for (int k = 0; k < 5; k++) \
            if (xoff[k] != 0xFFFFFFFFu) \
                cp_async8((bX) + xdst[k], xb + xoff[k] + (uint32_t)(ck)*16u); \
        _Pragma("unroll") \
        for (int k = 0; k < 6; k++) \
            if (woff[k] != 0xFFFFFFFFu) \
                cp_async16((bW) + wdst[k], wb + woff[k] + (uint32_t)(ck)*288u); \
        CP_COMMIT(); \
    } while (0)

    CV_ISSUE(0, sX0, sW0);

    ull acc[2][18];
    #pragma unroll
    for (int pp = 0; pp < 2; pp++)
        #pragma unroll
        for (int o = 0; o < 18; o++) acc[pp][o] = 0ULL;

    const int baserow = (tl + 2)*20 + nl + 2;

    for (int ck = 0; ck < 8; ck++) {
        const uint32_t bX = (ck & 1) ? sX1 : sX0;
        const uint32_t bW = (ck & 1) ? sW1 : sW0;
        CP_WAIT0();
        __syncthreads();
        if (ck < 7) CV_ISSUE(ck + 1, (ck & 1) ? sX0 : sX1, (ck & 1) ? sW0 : sW1);

        #pragma unroll
        for (int tap = 0; tap < 9; tap++) {
            const int dconst = (tap/3 - 1)*20 + (tap%3 - 1);
            const uint32_t xa = bX + (uint32_t)((baserow + dconst*ratio) * 8);
            const uint32_t wa = bW + (uint32_t)((r*9 + tap) * 1152);
            #pragma unroll
            for (int j = 0; j < 2; j++) {
                const uint32_t c2i = (uint32_t)(s*2 + j);
                ull xp0 = lds64(xa + c2i*1280u);
                ull xp1 = lds64(xa + c2i*1280u + 320u);   // +2 t rows
                const uint32_t wc = wa + c2i*144u;
                #pragma unroll
                for (int op = 0; op < 9; op++) {
                    ull w0, w1;
                    lds128u64(w0, w1, wc + (uint32_t)(op*16));
                    ffma2(acc[0][op*2],   xp0, w0);
                    ffma2(acc[0][op*2+1], xp0, w1);
                    ffma2(acc[1][op*2],   xp1, w0);
                    ffma2(acc[1][op*2+1], xp1, w1);
                }
            }
        }
    }

    #pragma unroll
    for (int pp = 0; pp < 2; pp++) {
        int pos = b*320 + (t0 + tl + pp*2)*16 + nl;
        float* dst = g_offp + ((size_t)((e*4 + s)*2 + r)*NPOS + pos)*18;
        #pragma unroll
        for (int o = 0; o < 18; o++) {
            float2 v = unpack2(acc[pp][o]);
            dst[o] = v.x + v.y;
        }
    }
#undef CV_ISSUE
}

// ---------------------------------------------------------------------------
// Kernel 3: deformable bilinear gather; epilogue writes A in bf16 hi/lo
// ---------------------------------------------------------------------------
__global__ void __launch_bounds__(256) k_gather(const float* __restrict__ x,
                                                const float* __restrict__ b1,
                                                const float* __restrict__ b2,
                                                float* __restrict__ out_ftmad,
                                                int write_ftmad) {
    int pos = blockIdx.x;
    int bb  = pos / 320; int rem = pos - bb*320;
    int t   = rem >> 4,  n = rem & 15;

    __shared__ int   s_off[2][9][4];
    __shared__ float s_coe[2][9][4];

    int tid = threadIdx.x;
    if (tid < 18) {
        int r = tid / 9, k = tid - r*9;
        int ratio = r + 1;
        const float* bias = r ? b2 : b1;
        float offt = bias[k], offn = bias[k + 9];
        #pragma unroll
        for (int q = 0; q < 32; q++) {
            const float* op = g_offp + ((size_t)(q*2 + r)*NPOS + pos)*18;
            offt += op[k];
            offn += op[k + 9];
        }
        float Tp1 = (float)(TT + 2*ratio - 1);
        float Np1 = (float)(TN + 2*ratio - 1);
        float post = (float)(t + ratio) + (float)((k/3 - 1)*ratio) + offt;
        float posn = (float)(n + ratio) + (float)((k%3 - 1)*ratio) + offn;
        float flt = floorf(post), fln = floorf(posn);
        float ltt = fminf(fmaxf(flt,       0.f), Tp1);
        float ltn = fminf(fmaxf(fln,       0.f), Np1);
        float rbt = fminf(fmaxf(flt + 1.f, 0.f), Tp1);
        float rbn = fminf(fmaxf(fln + 1.f, 0.f), Np1);
        float pct = fminf(fmaxf(post, 0.f), Tp1);
        float pcn = fminf(fmaxf(posn, 0.f), Np1);
        float wltt = 1.f - fabsf(pct - ltt);
        float wrbt = 1.f - fabsf(pct - rbt);
        float wltn = 1.f - fabsf(pcn - ltn);
        float wrbn = 1.f - fabsf(pcn - rbn);
        s_coe[r][k][0] = wltt * wltn;
        s_coe[r][k][1] = wrbt * wrbn;
        s_coe[r][k][2] = wrbt * wltn;
        s_coe[r][k][3] = wltt * wrbn;
        int ict[4] = {(int)ltt, (int)rbt, (int)rbt, (int)ltt};
        int icn[4] = {(int)ltn, (int)rbn, (int)ltn, (int)rbn};
        #pragma unroll
        for (int q = 0; q < 4; q++) {
            int ts = ict[q] - ratio, ns = icn[q] - ratio;
            s_off[r][k][q] = ((unsigned)ts < (unsigned)TT && (unsigned)ns < (unsigned)TN)
                           ? ((bb*TT + ts)*TN + ns)*TC : -1;
        }
    }
    __syncthreads();

    int c = tid * 4;
    float dx = 0.f, dy = 0.f, dz = 0.f, dw = 0.f;
    #pragma unroll
    for (int r = 0; r < 2; r++) {
        #pragma unroll
        for (int k = 0; k < 9; k++) {
            float fx = 0.f, fy = 0.f, fz = 0.f, fw = 0.f;
            #pragma unroll
            for (int q = 0; q < 4; q++) {
                int   o   = s_off[r][k][q];
                float coe = s_coe[r][k][q];
                if (o >= 0) {
                    float4 v = *(const float4*)(x + o + c);
                    fx = fmaf(coe, v.x, fx);
                    fy = fmaf(coe, v.y, fy);
                    fz = fmaf(coe, v.z, fz);
                    fw = fmaf(coe, v.w, fw);
                }
            }
            if (r == 1 && write_ftmad) {
                float4 ov = make_float4(fx, fy, fz, fw);
                *(float4*)(out_ftmad + (pos*9 + k)*1024 + c) = ov;
            }
            dx += fx; dy += fy; dz += fz; dw += fw;
        }
    }
    const float s = 1.f / 18.f;
    float4 dv = make_float4(dx*s, dy*s, dz*s, dw*s);

    BPack ph, pl;
    __nv_bfloat16 h;
    h = __float2bfloat16(dv.x); ph.h2[0].x = h; pl.h2[0].x = __float2bfloat16(dv.x - __bfloat162float(h));
    h = __float2bfloat16(dv.y); ph.h2[0].y = h; pl.h2[0].y = __float2bfloat16(dv.y - __bfloat162float(h));
    h = __float2bfloat16(dv.z); ph.h2[1].x = h; pl.h2[1].x = __float2bfloat16(dv.z - __bfloat162float(h));
    h = __float2bfloat16(dv.w); ph.h2[1].y = h; pl.h2[1].y = __float2bfloat16(dv.w - __bfloat162float(h));
    *(uint2*)(g_ahi + (long)pos*1024 + c) = ph.u;
    *(uint2*)(g_alo + (long)pos*1024 + c) = pl.u;
}

// ---------------------------------------------------------------------------
// Kernel 4: HMMA (mma.sync m16n8k16 bf16) split GEMM  out[2560,1024] = A @ W^T
// ---------------------------------------------------------------------------
#define KC       32
#define NSLAB    (1024/KC)
#define SA       80
#define S_AHI    0
#define S_ALO    (128*SA)
#define S_BHI    (2*128*SA)
#define S_BLO    (2*128*SA + 64*SA)
#define STG      (2*128*SA + 2*64*SA)
#define GSMEM    (2*STG)

__global__ void __launch_bounds__(256, 2) k_gemm_mma(float* __restrict__ out) {
    extern __shared__ __align__(16) char smem[];
    const uint32_t sb = smem_u32(smem);

    const int tid  = threadIdx.x;
    const int wid  = tid >> 5;
    const int lane = tid & 31;
    const int bx   = blockIdx.x;
    const int by   = blockIdx.y;
    const int wy   = wid & 3;
    const int wx   = wid >> 2;

    const __nv_bfloat16* pAhi = g_ahi + (long)by*128*1024;
    const __nv_bfloat16* pAlo = g_alo + (long)by*128*1024;
    const __nv_bfloat16* pBhi = g_bhi + (long)bx*64*1024;
    const __nv_bfloat16* pBlo = g_blo + (long)bx*64*1024;

    const int lrow = tid >> 2, lc4 = tid & 3;
    const long ga0 = (long)lrow*1024 + lc4*8;
    const long ga1 = (long)(lrow+64)*1024 + lc4*8;
    const uint32_t sa0 = (uint32_t)(lrow*SA + lc4*16);
    const uint32_t sa1 = (uint32_t)((lrow+64)*SA + lc4*16);

    float acc[2][4][4];
    #pragma unroll
    for (int i = 0; i < 2; i++)
        #pragma unroll
        for (int j = 0; j < 4; j++)
            #pragma unroll
            for (int q = 0; q < 4; q++) acc[i][j][q] = 0.f;

    const uint32_t laneA = (uint32_t)((lane & 15)*SA + (lane >> 4)*16);
    const uint32_t laneB = (uint32_t)((lane & 7)*SA + ((lane >> 3) & 1)*16);

    uint4 ra0 = *(const uint4*)(pAhi + ga0);
    uint4 ra1 = *(const uint4*)(pAhi + ga1);
    uint4 ra2 = *(const uint4*)(pAlo + ga0);
    uint4 ra3 = *(const uint4*)(pAlo + ga1);
    uint4 rb0 = *(const uint4*)(pBhi + ga0);
    uint4 rb1 = *(const uint4*)(pBlo + ga0);
    {
        *(uint4*)(smem + S_AHI + sa0) = ra0;
        *(uint4*)(smem + S_AHI + sa1) = ra1;
        *(uint4*)(smem + S_ALO + sa0) = ra2;
        *(uint4*)(smem + S_ALO + sa1) = ra3;
        *(uint4*)(smem + S_BHI + sa0) = rb0;
        *(uint4*)(smem + S_BLO + sa0) = rb1;
    }
    __syncthreads();

    int cur = 0;
    for (int s = 1; s <= NSLAB; s++) {
        bool more = (s < NSLAB);
        if (more) {
            long k0 = (long)s * KC;
            ra0 = *(const uint4*)(pAhi + ga0 + k0);
            ra1 = *(const uint4*)(pAhi + ga1 + k0);
            ra2 = *(const uint4*)(pAlo + ga0 + k0);
            ra3 = *(const uint4*)(pAlo + ga1 + k0);
            rb0 = *(const uint4*)(pBhi + ga0 + k0);
            rb1 = *(const uint4*)(pBlo + ga0 + k0);
        }

        uint32_t base = sb + cur*STG;
        #pragma unroll
        for (int kk = 0; kk < 2; kk++) {
            uint32_t kB = kk * 32;
            uint32_t ah[2][4], al[2][4], bh[4][2], bl[4][2];
            #pragma unroll
            for (int mi = 0; mi < 2; mi++) {
                uint32_t moff = (uint32_t)((wy*32 + mi*16)*SA) + kB + laneA;
                LDM4(ah[mi], base + S_AHI + moff);
                LDM4(al[mi], base + S_ALO + moff);
            }
            #pragma unroll
            for (int ni = 0; ni < 4; ni++) {
                uint32_t noff = (uint32_t)((wx*32 + ni*8)*SA) + kB + laneB;
                LDM2(bh[ni], base + S_BHI + noff);
                LDM2(bl[ni], base + S_BLO + noff);
            }
            #pragma unroll
            for (int mi = 0; mi < 2; mi++)
                #pragma unroll
                for (int ni = 0; ni < 4; ni++) {
                    mma_bf16(acc[mi][ni], ah[mi], bh[ni]);
                    mma_bf16(acc[mi][ni], ah[mi], bl[ni]);
                    mma_bf16(acc[mi][ni], al[mi], bh[ni]);
                }
        }

        if (more) {
            int nxt = cur ^ 1;
            char* nb = smem + nxt*STG;
            *(uint4*)(nb + S_AHI + sa0) = ra0;
            *(uint4*)(nb + S_AHI + sa1) = ra1;
            *(uint4*)(nb + S_ALO + sa0) = ra2;
            *(uint4*)(nb + S_ALO + sa1) = ra3;
            *(uint4*)(nb + S_BHI + sa0) = rb0;
            *(uint4*)(nb + S_BLO + sa0) = rb1;
            __syncthreads();
            cur = nxt;
        }
    }

    const int r0 = (lane >> 2);
    const int c0 = (lane & 3) * 2;
    #pragma unroll
    for (int mi = 0; mi < 2; mi++) {
        #pragma unroll
        for (int ni = 0; ni < 4; ni++) {
            long row = (long)by*128 + wy*32 + mi*16 + r0;
            long col = (long)bx*64 + wx*32 + ni*8 + c0;
            *(float2*)(out + row*1024 + col)       = make_float2(acc[mi][ni][0], acc[mi][ni][1]);
            *(float2*)(out + (row + 8)*1024 + col) = make_float2(acc[mi][ni][2], acc[mi][ni][3]);
        }
    }
}

// ---------------------------------------------------------------------------
extern "C" void kernel_launch(void* const* d_in, const int* in_sizes, int n_in,
                              void* d_out, int out_size) {
    const float* xf  = (const float*)d_in[0];  // person_features [8,20,16,1024]
    const float* Wh  = (const float*)d_in[1];  // W_hidden [1024,1024]
    const float* w1  = (const float*)d_in[2];  // p_w1 [18,1024,3,3]
    const float* bb1 = (const float*)d_in[3];  // p_b1 [18]
    const float* w2  = (const float*)d_in[4];  // p_w2 [18,1024,3,3]
    const float* bb2 = (const float*)d_in[5];  // p_b2 [18]
    (void)in_sizes; (void)n_in;

    float* out       = (float*)d_out;
    float* out_dyn   = out;                       // [2560,1024]
    float* out_ftmad = out + (long)NPOS * TC;     // [2560,9,1024]
    int write_ftmad  = (out_size >= NPOS*TC + NPOS*9*TC) ? 1 : 0;

    cudaFuncSetAttribute(k_gemm_mma, cudaFuncAttributeMaxDynamicSharedMemorySize,
                         GSMEM);
    cudaFuncSetAttribute(k_conv, cudaFuncAttributeMaxDynamicSharedMemorySize,
                         CV_SMEM);

    k_wtrans<<<(2*9*512*18 + 255)/256, 256>>>(w1, w2);
    k_wprep<<<1024, 256>>>(Wh);

    dim3 gconv(40, 8);
    k_conv<<<gconv, 256, CV_SMEM>>>(xf);

    k_gather<<<NPOS, 256>>>(xf, bb1, bb2, out_ftmad, write_ftmad);

    dim3 ggemm(16, 20);
    k_gemm_mma<<<ggemm, 256, GSMEM>>>(out_dyn);
}